// round 9
// baseline (speedup 1.0000x reference)
#include <cuda_runtime.h>
#include <cuda_fp16.h>
#include <cstdint>
#include <math.h>

#define B_  2
#define T_  2048
#define D_  2048
#define H_  16
#define KV_ 4
#define HD_ 128
#define M_  (B_*T_)    // 4096
#define KVD_ (KV_*HD_) // 512
#define NQKV 3072      // packed Q(2048) + K(512) + V(512)

// ---------------- scratch ----------------------------------------------------
__device__ float  g_QKVf[M_ * NQKV];
__device__ __half g_Xh[M_*D_];
__device__ __half g_W3h[NQKV*D_], g_W3l[NQKV*D_];
__device__ __half g_Woh[D_*D_],   g_Wol[D_*D_];
__device__ __half g_Qh[M_*D_],    g_Ql[M_*D_];
__device__ __half g_Kh2[M_*KVD_], g_Kl2[M_*KVD_];
__device__ __half g_Vth[M_*KVD_], g_Vtl[M_*KVD_];  // [(b*KV+g)*128+d][T]
__device__ __half g_Oh[M_*D_];

// ---------------- helpers -----------------------------------------------------
__device__ __forceinline__ void cvt2(float x, float y, uint32_t& h, uint32_t& l) {
    __half2 hh = __floats2half2_rn(x, y);
    float2 hf = __half22float2(hh);
    __half2 ll = __floats2half2_rn(x - hf.x, y - hf.y);
    h = *reinterpret_cast<uint32_t*>(&hh);
    l = *reinterpret_cast<uint32_t*>(&ll);
}
__device__ __forceinline__ uint32_t cvth(float x, float y) {
    __half2 hh = __floats2half2_rn(x, y);
    return *reinterpret_cast<uint32_t*>(&hh);
}
__device__ __forceinline__ void mma_f16(float* c, const uint32_t* a, const uint32_t* b) {
    asm volatile(
        "mma.sync.aligned.m16n8k16.row.col.f32.f16.f16.f32 "
        "{%0,%1,%2,%3}, {%4,%5,%6,%7}, {%8,%9}, {%0,%1,%2,%3};"
        : "+f"(c[0]), "+f"(c[1]), "+f"(c[2]), "+f"(c[3])
        : "r"(a[0]), "r"(a[1]), "r"(a[2]), "r"(a[3]), "r"(b[0]), "r"(b[1]));
}
__device__ __forceinline__ uint32_t s2u(const void* p) {
    uint32_t a;
    asm("{ .reg .u64 t; cvta.to.shared.u64 t, %1; cvt.u32.u64 %0, t; }" : "=r"(a) : "l"(p));
    return a;
}
#define LDSM4(r0, r1, r2, r3, addr) \
    asm volatile("ldmatrix.sync.aligned.m8n8.x4.shared.b16 {%0,%1,%2,%3}, [%4];" \
        : "=r"(r0), "=r"(r1), "=r"(r2), "=r"(r3) : "r"(addr))
#define CP16(dst, src) asm volatile("cp.async.cg.shared.global [%0], [%1], 16;" :: "r"(dst), "l"(src))
#define CPC   asm volatile("cp.async.commit_group;" ::: "memory")
#define CPW0  asm volatile("cp.async.wait_group 0;" ::: "memory")
#define CPW1  asm volatile("cp.async.wait_group 1;" ::: "memory")

// ---------------- pre-split kernels -------------------------------------------
__global__ void split_f32(const float* __restrict__ X,
                          __half* __restrict__ Xh, __half* __restrict__ Xl, int n4)
{
    int i = blockIdx.x * blockDim.x + threadIdx.x;
    if (i >= n4) return;
    float4 v = *(const float4*)(X + (size_t)i * 4);
    uint32_t h0, l0, h1, l1;
    cvt2(v.x, v.y, h0, l0);
    cvt2(v.z, v.w, h1, l1);
    *(uint2*)(Xh + (size_t)i * 4) = make_uint2(h0, h1);
    *(uint2*)(Xl + (size_t)i * 4) = make_uint2(l0, l1);
}
__global__ void split_hi(const float* __restrict__ X, __half* __restrict__ Xh, int n4)
{
    int i = blockIdx.x * blockDim.x + threadIdx.x;
    if (i >= n4) return;
    float4 v = *(const float4*)(X + (size_t)i * 4);
    *(uint2*)(Xh + (size_t)i * 4) = make_uint2(cvth(v.x, v.y), cvth(v.z, v.w));
}

__global__ void rope_split(const float* __restrict__ X,
                           __half* __restrict__ Xh, __half* __restrict__ Xl,
                           int nheads, float scale, int in_ld, int in_off, int total)
{
    int idx = blockIdx.x * blockDim.x + threadIdx.x;
    if (idx >= total) return;
    int j2 = idx & 31;
    int hh = (idx >> 5) % nheads;
    int m  = idx / (32 * nheads);
    int t  = m & (T_ - 1);

    size_t ri = (size_t)m * in_ld + in_off + hh * HD_;
    size_t ro = (size_t)m * (nheads * HD_) + hh * HD_;
    float2 a  = *(const float2*)(X + ri + j2*2);
    float2 bq = *(const float2*)(X + ri + 64 + j2*2);

    float inv0 = powf(10000.0f, -((float)(2 * (2*j2))     / 128.0f));
    float inv1 = powf(10000.0f, -((float)(2 * (2*j2 + 1)) / 128.0f));
    float s0, c0, s1, c1;
    sincosf((float)t * inv0, &s0, &c0);
    sincosf((float)t * inv1, &s1, &c1);

    float o0 = (a.x * c0 - bq.x * s0) * scale;
    float o1 = (a.y * c1 - bq.y * s1) * scale;
    float o2 = (bq.x * c0 + a.x * s0) * scale;
    float o3 = (bq.y * c1 + a.y * s1) * scale;

    uint32_t ph, pl;
    cvt2(o0, o1, ph, pl);
    *(uint32_t*)(Xh + ro + j2*2) = ph;
    *(uint32_t*)(Xl + ro + j2*2) = pl;
    cvt2(o2, o3, ph, pl);
    *(uint32_t*)(Xh + ro + 64 + j2*2) = ph;
    *(uint32_t*)(Xl + ro + 64 + j2*2) = pl;
}

__global__ void vtrans_split(const float* __restrict__ QKV,
                             __half* __restrict__ Vh, __half* __restrict__ Vl)
{
    __shared__ float tile[32][33];
    int bx = blockIdx.x, by = blockIdx.y, b = blockIdx.z;
    int tx = threadIdx.x, ty = threadIdx.y;
    #pragma unroll
    for (int i = 0; i < 4; i++) {
        int tt = bx*32 + ty + i*8;
        int dd = by*32 + tx;
        tile[ty + i*8][tx] = QKV[(size_t)(b*T_ + tt) * NQKV + 2560 + dd];
    }
    __syncthreads();
    #pragma unroll
    for (int i = 0; i < 4; i++) {
        int dd = by*32 + ty + i*8;
        int tt = bx*32 + tx;
        float v = tile[tx][ty + i*8];
        __half hv = __float2half_rn(v);
        __half lv = __float2half_rn(v - __half2float(hv));
        size_t o = (size_t)(b*KVD_ + dd) * T_ + tt;
        Vh[o] = hv; Vl[o] = lv;
    }
}

// ============================================================================
// 2-term fp16 GEMM with ldmatrix fragment loads (unchanged from round 8).
// ============================================================================
#define G2_BYTES (2*3*2560*4)

__global__ __launch_bounds__(256) void gemm_2t(
    const __half* __restrict__ Ah_g,
    const __half* __restrict__ Bh_g, const __half* __restrict__ Bl_g,
    float* __restrict__ C, int ldc, int K)
{
    extern __shared__ uint32_t su[];
    const uint32_t sb = s2u(su);
    const int tid = threadIdx.x, lane = tid & 31, w = tid >> 5;
    const int bm = blockIdx.y * 128, bn = blockIdx.x * 128;
    const int wm = (w & 1) * 64;
    const int wn = (w >> 1) * 32;
    const int g = lane >> 2, t = lane & 3;

    const int matid = tid >> 6;
    const __half* gp = (matid == 0) ? Ah_g : (matid == 1) ? Bh_g : Bl_g;
    const int rowb = (matid == 0) ? bm : bn;
    const int t64 = tid & 63;
    const int rb0 = t64 >> 2, cc = t64 & 3;
    const uint32_t dstb = sb + matid*10240 + rb0*80 + cc*16;
    const __half* srcb = gp + (size_t)(rowb + rb0) * K + cc * 8;
    const bool loader = (matid < 3);

    const int arow = wm + ((lane >> 3) & 1) * 8 + (lane & 7);
    const uint32_t aBase = sb + arow * 80 + (lane >> 4) * 16;
    const int brow = wn + (lane >> 4) * 8 + (lane & 7);
    const uint32_t bBase = sb + 10240 + brow * 80 + ((lane >> 3) & 1) * 16;

    float acc[4][4][4];
    #pragma unroll
    for (int mb = 0; mb < 4; mb++)
        #pragma unroll
        for (int nb = 0; nb < 4; nb++)
            #pragma unroll
            for (int i = 0; i < 4; i++) acc[mb][nb][i] = 0.f;

    if (loader) {
        #pragma unroll
        for (int i = 0; i < 8; i++)
            CP16(dstb + i*1280, srcb + (size_t)(16*i) * K);
    }
    CPC;

    const int NT = K >> 5;
    for (int kt = 0; kt < NT; kt++) {
        const int stg = kt & 1;
        const uint32_t stgoff = stg * 30720;
        CPW0;
        __syncthreads();
        if (kt + 1 < NT && loader) {
            const __half* s = srcb + (kt + 1) * 32;
            const uint32_t d2 = dstb + (stg ^ 1) * 30720;
            #pragma unroll
            for (int i = 0; i < 8; i++)
                CP16(d2 + i*1280, s + (size_t)(16*i) * K);
        }
        CPC;

        #pragma unroll
        for (int ks = 0; ks < 2; ks++) {
            uint32_t ah[4][4], bh[4][2], bl[4][2];
            #pragma unroll
            for (int mb = 0; mb < 4; mb++)
                LDSM4(ah[mb][0], ah[mb][1], ah[mb][2], ah[mb][3],
                      aBase + stgoff + mb*1280 + ks*32);
            #pragma unroll
            for (int nbp = 0; nbp < 2; nbp++) {
                LDSM4(bh[2*nbp][0], bh[2*nbp][1], bh[2*nbp+1][0], bh[2*nbp+1][1],
                      bBase + stgoff + nbp*1280 + ks*32);
                LDSM4(bl[2*nbp][0], bl[2*nbp][1], bl[2*nbp+1][0], bl[2*nbp+1][1],
                      bBase + stgoff + 10240 + nbp*1280 + ks*32);
            }
            #pragma unroll
            for (int nb = 0; nb < 4; nb++)
                #pragma unroll
                for (int mb = 0; mb < 4; mb++) {
                    mma_f16(acc[mb][nb], ah[mb], bh[nb]);
                    mma_f16(acc[mb][nb], ah[mb], bl[nb]);
                }
        }
    }

    #pragma unroll
    for (int mb = 0; mb < 4; mb++) {
        int r0 = bm + wm + mb * 16 + g;
        #pragma unroll
        for (int nb = 0; nb < 4; nb++) {
            int ccn = bn + wn + nb * 8 + 2 * t;
            *(float2*)(C + (size_t)r0 * ldc + ccn)       = make_float2(acc[mb][nb][0], acc[mb][nb][1]);
            *(float2*)(C + (size_t)(r0 + 8) * ldc + ccn) = make_float2(acc[mb][nb][2], acc[mb][nb][3]);
        }
    }
}

// ============================================================================
// FA2-style flash attention: warps partition q only; S/P stay in registers.
// CTA = 128 q rows, 8 warps (16 rows each). KV tile = 128.
// ============================================================================
#define AP 68
#define QH_OFF 0
#define QL_OFF (128*AP)
#define KH_OFF (2*128*AP)
#define KL_OFF (3*128*AP)
#define VH_OFF (4*128*AP)
#define VL_OFF (5*128*AP)
#define FA_SMEM_BYTES (6*128*AP*4)   // 208896 B

__global__ __launch_bounds__(256, 1) void flash_attn_fa2(
    const __half* __restrict__ Qh_g, const __half* __restrict__ Ql_g,
    const __half* __restrict__ Kh_g, const __half* __restrict__ Kl_g,
    const __half* __restrict__ Vh_g, const __half* __restrict__ Vl_g,
    __half* __restrict__ Oh_g)
{
    extern __shared__ uint32_t su[];
    const uint32_t sb = s2u(su);

    const int tid = threadIdx.x, lane = tid & 31, w = tid >> 5;
    const int qt = blockIdx.x, h = blockIdx.y, b = blockIdx.z;
    const int gq = h >> 2;
    const int q0 = qt * 128;
    const int g = lane >> 2, t = lane & 3;

    // loader decomposition (256 threads; vm selects hi/lo plane)
    const int vm = tid >> 7;
    const int t128 = tid & 127;
    const int qr = t128 >> 4, qc = t128 & 15;

    auto issueK = [&](int s0k) {
        const __half* src = (vm ? Kl_g : Kh_g) + (size_t)(b*T_ + s0k + qr) * KVD_ + gq*HD_ + qc*8;
        uint32_t dst = sb + (uint32_t)(KH_OFF + vm*(128*AP))*4 + qr*272 + qc*16;
        #pragma unroll
        for (int i = 0; i < 16; i++)
            CP16(dst + i*8*272, src + (size_t)(8*i) * KVD_);
    };
    auto issueV = [&](int s0v) {
        const __half* src = (vm ? Vl_g : Vh_g) + ((size_t)(b*KV_ + gq)*HD_ + qr) * T_ + s0v + qc*8;
        uint32_t dst = sb + (uint32_t)(VH_OFF + vm*(128*AP))*4 + qr*272 + qc*16;
        #pragma unroll
        for (int i = 0; i < 16; i++)
            CP16(dst + i*8*272, src + (size_t)(8*i) * T_);
    };

    // prologue: Q (128 rows) + K(0), then V(0)
    {
        const __half* src = (vm ? Ql_g : Qh_g) + (size_t)(b*T_ + q0 + qr) * D_ + h*HD_ + qc*8;
        uint32_t dst = sb + (uint32_t)(QH_OFF + vm*(128*AP))*4 + qr*272 + qc*16;
        #pragma unroll
        for (int i = 0; i < 16; i++)
            CP16(dst + i*8*272, src + (size_t)(8*i) * D_);
        issueK(0);
    }
    CPC;
    issueV(0);
    CPC;

    // ldmatrix per-lane bases
    const int arow = 16*w + ((lane >> 3) & 1) * 8 + (lane & 7);
    const uint32_t aBase = sb + arow * 272 + (lane >> 4) * 16;
    const uint32_t bBase = sb + ((lane >> 4) * 8 + (lane & 7)) * 272 + ((lane >> 3) & 1) * 16;

    float m0 = -INFINITY, m1 = -INFINITY, l0 = 0.f, l1 = 0.f;
    float oacc[16][4];
    #pragma unroll
    for (int j = 0; j < 16; j++)
        #pragma unroll
        for (int i = 0; i < 4; i++) oacc[j][i] = 0.f;

    for (int it = 0; it < 16; it++) {
        CPW1;               // K(it) ready (V(it) may be in flight)
        __syncthreads();

        // ---- S = Q K^T : warp's 16 rows x full 128 cols, in registers ----
        float sfr[16][4];
        #pragma unroll
        for (int j = 0; j < 16; j++)
            #pragma unroll
            for (int i = 0; i < 4; i++) sfr[j][i] = 0.f;

        #pragma unroll
        for (int k16 = 0; k16 < 8; k16++) {
            uint32_t ah[4], al[4];
            LDSM4(ah[0], ah[1], ah[2], ah[3], aBase + QH_OFF*4 + k16*32);
            LDSM4(al[0], al[1], al[2], al[3], aBase + QL_OFF*4 + k16*32);
            #pragma unroll
            for (int np = 0; np < 8; np++) {
                uint32_t bh[4], bl[4];
                LDSM4(bh[0], bh[1], bh[2], bh[3], bBase + KH_OFF*4 + np*4352 + k16*32);
                LDSM4(bl[0], bl[1], bl[2], bl[3], bBase + KL_OFF*4 + np*4352 + k16*32);
                mma_f16(sfr[2*np],   ah, bh);     mma_f16(sfr[2*np],   ah, bl);
                mma_f16(sfr[2*np],   al, bh);
                mma_f16(sfr[2*np+1], ah, bh + 2); mma_f16(sfr[2*np+1], ah, bl + 2);
                mma_f16(sfr[2*np+1], al, bh + 2);
            }
        }
        __syncthreads();                       // all warps done reading K
        if (it + 1 < 16) issueK((it + 1) * 128);
        CPC;                                   // K load overlaps softmax below

        // ---- softmax: registers + shfl only ----
        float mt0 = -INFINITY, mt1 = -INFINITY;
        #pragma unroll
        for (int j = 0; j < 16; j++) {
            mt0 = fmaxf(mt0, fmaxf(sfr[j][0], sfr[j][1]));
            mt1 = fmaxf(mt1, fmaxf(sfr[j][2], sfr[j][3]));
        }
        mt0 = fmaxf(mt0, __shfl_xor_sync(0xffffffffu, mt0, 1));
        mt0 = fmaxf(mt0, __shfl_xor_sync(0xffffffffu, mt0, 2));
        mt1 = fmaxf(mt1, __shfl_xor_sync(0xffffffffu, mt1, 1));
        mt1 = fmaxf(mt1, __shfl_xor_sync(0xffffffffu, mt1, 2));
        float mn0 = fmaxf(m0, mt0), mn1 = fmaxf(m1, mt1);
        float rs0 = __expf(m0 - mn0), rs1 = __expf(m1 - mn1);
        m0 = mn0; m1 = mn1;
        float ps0 = 0.f, ps1 = 0.f;
        #pragma unroll
        for (int j = 0; j < 16; j++) {
            sfr[j][0] = __expf(sfr[j][0] - m0);
            sfr[j][1] = __expf(sfr[j][1] - m0);
            sfr[j][2] = __expf(sfr[j][2] - m1);
            sfr[j][3] = __expf(sfr[j][3] - m1);
            ps0 += sfr[j][0] + sfr[j][1];
            ps1 += sfr[j][2] + sfr[j][3];
        }
        ps0 += __shfl_xor_sync(0xffffffffu, ps0, 1);
        ps0 += __shfl_xor_sync(0xffffffffu, ps0, 2);
        ps1 += __shfl_xor_sync(0xffffffffu, ps1, 1);
        ps1 += __shfl_xor_sync(0xffffffffu, ps1, 2);
        l0 = l0 * rs0 + ps0;
        l1 = l1 * rs1 + ps1;
        #pragma unroll
        for (int j = 0; j < 16; j++) {
            oacc[j][0] *= rs0; oacc[j][1] *= rs0;
            oacc[j][2] *= rs1; oacc[j][3] *= rs1;
        }

        if (it < 15) { CPW1; } else { CPW0; }  // V(it) ready
        __syncthreads();

        // ---- O += P V : P fragments straight from S registers ----
        #pragma unroll
        for (int ks = 0; ks < 8; ks++) {
            uint32_t ph[4], pl[4];
            cvt2(sfr[2*ks][0],   sfr[2*ks][1],   ph[0], pl[0]);
            cvt2(sfr[2*ks][2],   sfr[2*ks][3],   ph[1], pl[1]);
            cvt2(sfr[2*ks+1][0], sfr[2*ks+1][1], ph[2], pl[2]);
            cvt2(sfr[2*ks+1][2], sfr[2*ks+1][3], ph[3], pl[3]);
            #pragma unroll
            for (int np = 0; np < 8; np++) {
                uint32_t bh[4], bl[4];
                LDSM4(bh[0], bh[1], bh[2], bh[3], bBase + VH_OFF*4 + np*4352 + ks*32);
                LDSM4(bl[0], bl[1], bl[2], bl[3], bBase + VL_OFF*4 + np*4352 + ks*32);
                mma_f16(oacc[2*np],   ph, bh);     mma_f16(oacc[2*np],   ph, bl);
                mma_f16(oacc[2*np],   pl, bh);
                mma_f16(oacc[2*np+1], ph, bh + 2); mma_f16(oacc[2*np+1], ph, bl + 2);
                mma_f16(oacc[2*np+1], pl, bh + 2);
            }
        }
        __syncthreads();                       // all warps done reading V
        if (it + 1 < 16) issueV((it + 1) * 128);
        CPC;
    }

    // ---- epilogue: normalize, write fp16 hi ----
    float inv0 = 1.0f / l0, inv1 = 1.0f / l1;
    #pragma unroll
    for (int j = 0; j < 16; j++) {
        int col = h*HD_ + j*8 + 2*t;
        size_t o0 = (size_t)(b*T_ + q0 + 16*w + g) * D_ + col;
        size_t o1 = o0 + (size_t)8 * D_;
        *(uint32_t*)(Oh_g + o0) = cvth(oacc[j][0]*inv0, oacc[j][1]*inv0);
        *(uint32_t*)(Oh_g + o1) = cvth(oacc[j][2]*inv1, oacc[j][3]*inv1);
    }
}

// ---------------- launch ------------------------------------------------------
extern "C" void kernel_launch(void* const* d_in, const int* in_sizes, int n_in,
                              void* d_out, int out_size)
{
    const float* x  = (const float*)d_in[0];
    const float* wq = (const float*)d_in[1];
    const float* wk = (const float*)d_in[2];
    const float* wv = (const float*)d_in[3];
    const float* wo = (const float*)d_in[4];
    float* out = (float*)d_out;

    float *pQKV;
    __half *pXh, *pW3h, *pW3l, *pWoh, *pWol;
    __half *pQh, *pQl, *pKh, *pKl, *pVth, *pVtl, *pOh;
    cudaGetSymbolAddress((void**)&pQKV, g_QKVf);
    cudaGetSymbolAddress((void**)&pXh, g_Xh);
    cudaGetSymbolAddress((void**)&pW3h, g_W3h); cudaGetSymbolAddress((void**)&pW3l, g_W3l);
    cudaGetSymbolAddress((void**)&pWoh, g_Woh); cudaGetSymbolAddress((void**)&pWol, g_Wol);
    cudaGetSymbolAddress((void**)&pQh, g_Qh);   cudaGetSymbolAddress((void**)&pQl, g_Ql);
    cudaGetSymbolAddress((void**)&pKh, g_Kh2);  cudaGetSymbolAddress((void**)&pKl, g_Kl2);
    cudaGetSymbolAddress((void**)&pVth, g_Vth); cudaGetSymbolAddress((void**)&pVtl, g_Vtl);
    cudaGetSymbolAddress((void**)&pOh, g_Oh);

    cudaFuncSetAttribute(gemm_2t, cudaFuncAttributeMaxDynamicSharedMemorySize, G2_BYTES);
    cudaFuncSetAttribute(flash_attn_fa2, cudaFuncAttributeMaxDynamicSharedMemorySize, FA_SMEM_BYTES);

    split_hi<<<(M_*D_/4)/256, 256>>>(x, pXh, M_*D_/4);
    split_f32<<<(D_*D_/4)/256,   256>>>(wq, pW3h,                      pW3l,                      D_*D_/4);
    split_f32<<<(KVD_*D_/4)/256, 256>>>(wk, pW3h + (size_t)2048*2048,  pW3l + (size_t)2048*2048,  KVD_*D_/4);
    split_f32<<<(KVD_*D_/4)/256, 256>>>(wv, pW3h + (size_t)2560*2048,  pW3l + (size_t)2560*2048,  KVD_*D_/4);
    split_f32<<<(D_*D_/4)/256,   256>>>(wo, pWoh, pWol, D_*D_/4);

    gemm_2t<<<dim3(NQKV/128, M_/128), 256, G2_BYTES>>>(pXh, pW3h, pW3l, pQKV, NQKV, D_);

    const float scale = 0.08838834764831845f;
    rope_split<<<(M_*H_*32)/256,  256>>>(pQKV, pQh, pQl, H_,  scale, NQKV, 0,    M_*H_*32);
    rope_split<<<(M_*KV_*32)/256, 256>>>(pQKV, pKh, pKl, KV_, 1.0f,  NQKV, 2048, M_*KV_*32);
    vtrans_split<<<dim3(T_/32, KVD_/32, B_), dim3(32, 8)>>>(pQKV, pVth, pVtl);

    flash_attn_fa2<<<dim3(T_/128, H_, B_), 256, FA_SMEM_BYTES>>>(
        pQh, pQl, pKh, pKl, pVth, pVtl, pOh);

    gemm_2t<<<dim3(D_/128, M_/128), 256, G2_BYTES>>>(pOh, pWoh, pWol, out, D_, D_);
}

// round 10
// speedup vs baseline: 1.7040x; 1.7040x over previous
#include <cuda_runtime.h>
#include <cuda_fp16.h>
#include <cstdint>
#include <math.h>

#define B_  2
#define T_  2048
#define D_  2048
#define H_  16
#define KV_ 4
#define HD_ 128
#define M_  (B_*T_)    // 4096
#define KVD_ (KV_*HD_) // 512
#define NQKV 3072      // packed Q(2048) + K(512) + V(512)

// ---------------- scratch ----------------------------------------------------
__device__ float  g_QKVf[M_ * NQKV];
__device__ __half g_Xh[M_*D_];
__device__ __half g_W3h[NQKV*D_], g_W3l[NQKV*D_];
__device__ __half g_Woh[D_*D_],   g_Wol[D_*D_];
__device__ __half g_Qh[M_*D_],    g_Ql[M_*D_];
__device__ __half g_Kh2[M_*KVD_], g_Kl2[M_*KVD_];
__device__ __half g_Vth[M_*KVD_];                  // [(b*KV+g)*128+d][T], hi only
__device__ __half g_Oh[M_*D_];

// ---------------- helpers -----------------------------------------------------
__device__ __forceinline__ void cvt2(float x, float y, uint32_t& h, uint32_t& l) {
    __half2 hh = __floats2half2_rn(x, y);
    float2 hf = __half22float2(hh);
    __half2 ll = __floats2half2_rn(x - hf.x, y - hf.y);
    h = *reinterpret_cast<uint32_t*>(&hh);
    l = *reinterpret_cast<uint32_t*>(&ll);
}
__device__ __forceinline__ uint32_t cvth(float x, float y) {
    __half2 hh = __floats2half2_rn(x, y);
    return *reinterpret_cast<uint32_t*>(&hh);
}
__device__ __forceinline__ void mma_f16(float* c, const uint32_t* a, const uint32_t* b) {
    asm volatile(
        "mma.sync.aligned.m16n8k16.row.col.f32.f16.f16.f32 "
        "{%0,%1,%2,%3}, {%4,%5,%6,%7}, {%8,%9}, {%0,%1,%2,%3};"
        : "+f"(c[0]), "+f"(c[1]), "+f"(c[2]), "+f"(c[3])
        : "r"(a[0]), "r"(a[1]), "r"(a[2]), "r"(a[3]), "r"(b[0]), "r"(b[1]));
}
__device__ __forceinline__ uint32_t s2u(const void* p) {
    uint32_t a;
    asm("{ .reg .u64 t; cvta.to.shared.u64 t, %1; cvt.u32.u64 %0, t; }" : "=r"(a) : "l"(p));
    return a;
}
#define LDSM4(r0, r1, r2, r3, addr) \
    asm volatile("ldmatrix.sync.aligned.m8n8.x4.shared.b16 {%0,%1,%2,%3}, [%4];" \
        : "=r"(r0), "=r"(r1), "=r"(r2), "=r"(r3) : "r"(addr))
#define CP16(dst, src) asm volatile("cp.async.cg.shared.global [%0], [%1], 16;" :: "r"(dst), "l"(src))
#define CPC   asm volatile("cp.async.commit_group;" ::: "memory")
#define CPW0  asm volatile("cp.async.wait_group 0;" ::: "memory")
#define CPW1  asm volatile("cp.async.wait_group 1;" ::: "memory")

// ---------------- pre-split kernels -------------------------------------------
__global__ void split_f32(const float* __restrict__ X,
                          __half* __restrict__ Xh, __half* __restrict__ Xl, int n4)
{
    int i = blockIdx.x * blockDim.x + threadIdx.x;
    if (i >= n4) return;
    float4 v = *(const float4*)(X + (size_t)i * 4);
    uint32_t h0, l0, h1, l1;
    cvt2(v.x, v.y, h0, l0);
    cvt2(v.z, v.w, h1, l1);
    *(uint2*)(Xh + (size_t)i * 4) = make_uint2(h0, h1);
    *(uint2*)(Xl + (size_t)i * 4) = make_uint2(l0, l1);
}
__global__ void split_hi(const float* __restrict__ X, __half* __restrict__ Xh, int n4)
{
    int i = blockIdx.x * blockDim.x + threadIdx.x;
    if (i >= n4) return;
    float4 v = *(const float4*)(X + (size_t)i * 4);
    *(uint2*)(Xh + (size_t)i * 4) = make_uint2(cvth(v.x, v.y), cvth(v.z, v.w));
}

__global__ void rope_split(const float* __restrict__ X,
                           __half* __restrict__ Xh, __half* __restrict__ Xl,
                           int nheads, float scale, int in_ld, int in_off, int total)
{
    int idx = blockIdx.x * blockDim.x + threadIdx.x;
    if (idx >= total) return;
    int j2 = idx & 31;
    int hh = (idx >> 5) % nheads;
    int m  = idx / (32 * nheads);
    int t  = m & (T_ - 1);

    size_t ri = (size_t)m * in_ld + in_off + hh * HD_;
    size_t ro = (size_t)m * (nheads * HD_) + hh * HD_;
    float2 a  = *(const float2*)(X + ri + j2*2);
    float2 bq = *(const float2*)(X + ri + 64 + j2*2);

    float inv0 = powf(10000.0f, -((float)(2 * (2*j2))     / 128.0f));
    float inv1 = powf(10000.0f, -((float)(2 * (2*j2 + 1)) / 128.0f));
    float s0, c0, s1, c1;
    sincosf((float)t * inv0, &s0, &c0);
    sincosf((float)t * inv1, &s1, &c1);

    float o0 = (a.x * c0 - bq.x * s0) * scale;
    float o1 = (a.y * c1 - bq.y * s1) * scale;
    float o2 = (bq.x * c0 + a.x * s0) * scale;
    float o3 = (bq.y * c1 + a.y * s1) * scale;

    uint32_t ph, pl;
    cvt2(o0, o1, ph, pl);
    *(uint32_t*)(Xh + ro + j2*2) = ph;
    *(uint32_t*)(Xl + ro + j2*2) = pl;
    cvt2(o2, o3, ph, pl);
    *(uint32_t*)(Xh + ro + 64 + j2*2) = ph;
    *(uint32_t*)(Xl + ro + 64 + j2*2) = pl;
}

// V transpose: packed QKVf col 2560+ -> [(b*KV+g)*128+d][t] fp16 hi only
__global__ void vtrans_split(const float* __restrict__ QKV, __half* __restrict__ Vh)
{
    __shared__ float tile[32][33];
    int bx = blockIdx.x, by = blockIdx.y, b = blockIdx.z;
    int tx = threadIdx.x, ty = threadIdx.y;
    #pragma unroll
    for (int i = 0; i < 4; i++) {
        int tt = bx*32 + ty + i*8;
        int dd = by*32 + tx;
        tile[ty + i*8][tx] = QKV[(size_t)(b*T_ + tt) * NQKV + 2560 + dd];
    }
    __syncthreads();
    #pragma unroll
    for (int i = 0; i < 4; i++) {
        int dd = by*32 + ty + i*8;
        int tt = bx*32 + tx;
        float v = tile[tx][ty + i*8];
        Vh[(size_t)(b*KVD_ + dd) * T_ + tt] = __float2half_rn(v);
    }
}

// ============================================================================
// 2-term fp16 GEMM with ldmatrix fragment loads (unchanged from round 8).
// ============================================================================
#define G2_BYTES (2*3*2560*4)

__global__ __launch_bounds__(256) void gemm_2t(
    const __half* __restrict__ Ah_g,
    const __half* __restrict__ Bh_g, const __half* __restrict__ Bl_g,
    float* __restrict__ C, int ldc, int K)
{
    extern __shared__ uint32_t su[];
    const uint32_t sb = s2u(su);
    const int tid = threadIdx.x, lane = tid & 31, w = tid >> 5;
    const int bm = blockIdx.y * 128, bn = blockIdx.x * 128;
    const int wm = (w & 1) * 64;
    const int wn = (w >> 1) * 32;
    const int g = lane >> 2, t = lane & 3;

    const int matid = tid >> 6;
    const __half* gp = (matid == 0) ? Ah_g : (matid == 1) ? Bh_g : Bl_g;
    const int rowb = (matid == 0) ? bm : bn;
    const int t64 = tid & 63;
    const int rb0 = t64 >> 2, cc = t64 & 3;
    const uint32_t dstb = sb + matid*10240 + rb0*80 + cc*16;
    const __half* srcb = gp + (size_t)(rowb + rb0) * K + cc * 8;
    const bool loader = (matid < 3);

    const int arow = wm + ((lane >> 3) & 1) * 8 + (lane & 7);
    const uint32_t aBase = sb + arow * 80 + (lane >> 4) * 16;
    const int brow = wn + (lane >> 4) * 8 + (lane & 7);
    const uint32_t bBase = sb + 10240 + brow * 80 + ((lane >> 3) & 1) * 16;

    float acc[4][4][4];
    #pragma unroll
    for (int mb = 0; mb < 4; mb++)
        #pragma unroll
        for (int nb = 0; nb < 4; nb++)
            #pragma unroll
            for (int i = 0; i < 4; i++) acc[mb][nb][i] = 0.f;

    if (loader) {
        #pragma unroll
        for (int i = 0; i < 8; i++)
            CP16(dstb + i*1280, srcb + (size_t)(16*i) * K);
    }
    CPC;

    const int NT = K >> 5;
    for (int kt = 0; kt < NT; kt++) {
        const int stg = kt & 1;
        const uint32_t stgoff = stg * 30720;
        CPW0;
        __syncthreads();
        if (kt + 1 < NT && loader) {
            const __half* s = srcb + (kt + 1) * 32;
            const uint32_t d2 = dstb + (stg ^ 1) * 30720;
            #pragma unroll
            for (int i = 0; i < 8; i++)
                CP16(d2 + i*1280, s + (size_t)(16*i) * K);
        }
        CPC;

        #pragma unroll
        for (int ks = 0; ks < 2; ks++) {
            uint32_t ah[4][4], bh[4][2], bl[4][2];
            #pragma unroll
            for (int mb = 0; mb < 4; mb++)
                LDSM4(ah[mb][0], ah[mb][1], ah[mb][2], ah[mb][3],
                      aBase + stgoff + mb*1280 + ks*32);
            #pragma unroll
            for (int nbp = 0; nbp < 2; nbp++) {
                LDSM4(bh[2*nbp][0], bh[2*nbp][1], bh[2*nbp+1][0], bh[2*nbp+1][1],
                      bBase + stgoff + nbp*1280 + ks*32);
                LDSM4(bl[2*nbp][0], bl[2*nbp][1], bl[2*nbp+1][0], bl[2*nbp+1][1],
                      bBase + stgoff + 10240 + nbp*1280 + ks*32);
            }
            #pragma unroll
            for (int nb = 0; nb < 4; nb++)
                #pragma unroll
                for (int mb = 0; mb < 4; mb++) {
                    mma_f16(acc[mb][nb], ah[mb], bh[nb]);
                    mma_f16(acc[mb][nb], ah[mb], bl[nb]);
                }
        }
    }

    #pragma unroll
    for (int mb = 0; mb < 4; mb++) {
        int r0 = bm + wm + mb * 16 + g;
        #pragma unroll
        for (int nb = 0; nb < 4; nb++) {
            int ccn = bn + wn + nb * 8 + 2 * t;
            *(float2*)(C + (size_t)r0 * ldc + ccn)       = make_float2(acc[mb][nb][0], acc[mb][nb][1]);
            *(float2*)(C + (size_t)(r0 + 8) * ldc + ccn) = make_float2(acc[mb][nb][2], acc[mb][nb][3]);
        }
    }
}

// ============================================================================
// flash attention: 3-term QK, plain-fp16 PV. Round-8 structure.
// ============================================================================
#define AP 68
#define QH_OFF 0
#define QL_OFF (64*AP)
#define KH_OFF (128*AP)
#define KL_OFF (256*AP)
#define VH_OFF (384*AP)
#define PH_OFF (512*AP)
#define ST_OFF (576*AP)
#define FA_SMEM_BYTES ((ST_OFF + 64*3 + 4*64*2) * 4)   // ~159 KB

__global__ __launch_bounds__(256) void flash_attn_h3(
    const __half* __restrict__ Qh_g, const __half* __restrict__ Ql_g,
    const __half* __restrict__ Kh_g, const __half* __restrict__ Kl_g,
    const __half* __restrict__ Vh_g,
    __half* __restrict__ Oh_g)
{
    extern __shared__ uint32_t su[];
    const uint32_t sb = s2u(su);
    uint32_t* Ph = su + PH_OFF;
    float* m_s  = (float*)(su + ST_OFF);
    float* l_s  = m_s + 64;
    float* rs_s = l_s + 64;
    float* pmax = rs_s + 64;
    float* psum = pmax + 4*64;

    const int tid = threadIdx.x, lane = tid & 31, w = tid >> 5;
    const int qt = blockIdx.x, h = blockIdx.y, b = blockIdx.z;
    const int gq = h >> 2;
    const int q0 = qt * 64;
    const int wm = (w & 1) * 32;
    const int wn = (w >> 1) * 32;
    const int g = lane >> 2, t = lane & 3;

    // loader decomposition: K/Q use vm (hi/lo plane) x 128 threads; V uses all 256
    const int vm = tid >> 7;
    const int t128 = tid & 127;
    const int qr = t128 >> 4, qc = t128 & 15;
    const int vr = tid >> 4, vc = tid & 15;     // vr 0..15, vc 0..15

    auto issueK = [&](int s0k) {
        const __half* src = (vm ? Kl_g : Kh_g) + (size_t)(b*T_ + s0k + qr) * KVD_ + gq*HD_ + qc*8;
        uint32_t dst = sb + (uint32_t)(KH_OFF + vm*(128*AP))*4 + qr*272 + qc*16;
        #pragma unroll
        for (int i = 0; i < 16; i++)
            CP16(dst + i*8*272, src + (size_t)(8*i) * KVD_);
    };
    auto issueV = [&](int s0v) {
        const __half* src = Vh_g + ((size_t)(b*KV_ + gq)*HD_ + vr) * T_ + s0v + vc*8;
        uint32_t dst = sb + (uint32_t)VH_OFF*4 + vr*272 + vc*16;
        #pragma unroll
        for (int i = 0; i < 8; i++)
            CP16(dst + i*16*272, src + (size_t)(16*i) * T_);
    };

    {
        const __half* src = (vm ? Ql_g : Qh_g) + (size_t)(b*T_ + q0 + qr) * D_ + h*HD_ + qc*8;
        uint32_t dst = sb + (uint32_t)(QH_OFF + vm*(64*AP))*4 + qr*272 + qc*16;
        #pragma unroll
        for (int i = 0; i < 8; i++)
            CP16(dst + i*8*272, src + (size_t)(8*i) * D_);
        issueK(0);
    }
    CPC;
    issueV(0);
    CPC;

    if (tid < 64) { m_s[tid] = -INFINITY; l_s[tid] = 0.f; }

    float acc[2][4][4];
    #pragma unroll
    for (int mb = 0; mb < 2; mb++)
        #pragma unroll
        for (int nb = 0; nb < 4; nb++)
            #pragma unroll
            for (int i = 0; i < 4; i++) acc[mb][nb][i] = 0.f;

    // ldmatrix per-lane bases
    const int arow = wm + ((lane >> 3) & 1) * 8 + (lane & 7);
    const uint32_t aBase = sb + arow * 272 + (lane >> 4) * 16;
    const int brow = wn + (lane >> 4) * 8 + (lane & 7);
    const uint32_t bBase = sb + brow * 272 + ((lane >> 3) & 1) * 16;

    for (int it = 0; it < 16; it++) {
        CPW1;
        __syncthreads();

        // ---- S = Q K^T (3-term) ----
        float sfr[2][4][4];
        #pragma unroll
        for (int mb = 0; mb < 2; mb++)
            #pragma unroll
            for (int nb = 0; nb < 4; nb++)
                #pragma unroll
                for (int i = 0; i < 4; i++) sfr[mb][nb][i] = 0.f;

        #pragma unroll
        for (int k16 = 0; k16 < 8; k16++) {
            uint32_t ah[2][4], al[2][4], bh[4][2], bl[4][2];
            #pragma unroll
            for (int mb = 0; mb < 2; mb++) {
                LDSM4(ah[mb][0], ah[mb][1], ah[mb][2], ah[mb][3],
                      aBase + QH_OFF*4 + mb*16*272 + k16*32);
                LDSM4(al[mb][0], al[mb][1], al[mb][2], al[mb][3],
                      aBase + QL_OFF*4 + mb*16*272 + k16*32);
            }
            #pragma unroll
            for (int nbp = 0; nbp < 2; nbp++) {
                LDSM4(bh[2*nbp][0], bh[2*nbp][1], bh[2*nbp+1][0], bh[2*nbp+1][1],
                      bBase + KH_OFF*4 + nbp*16*272 + k16*32);
                LDSM4(bl[2*nbp][0], bl[2*nbp][1], bl[2*nbp+1][0], bl[2*nbp+1][1],
                      bBase + KL_OFF*4 + nbp*16*272 + k16*32);
            }
            #pragma unroll
            for (int nb = 0; nb < 4; nb++)
                #pragma unroll
                for (int mb = 0; mb < 2; mb++) {
                    mma_f16(sfr[mb][nb], ah[mb], bh[nb]);
                    mma_f16(sfr[mb][nb], ah[mb], bl[nb]);
                    mma_f16(sfr[mb][nb], al[mb], bh[nb]);
                }
        }

        // ---- row max ----
        #pragma unroll
        for (int mb = 0; mb < 2; mb++) {
            float m0 = -INFINITY, m1 = -INFINITY;
            #pragma unroll
            for (int nb = 0; nb < 4; nb++) {
                m0 = fmaxf(m0, fmaxf(sfr[mb][nb][0], sfr[mb][nb][1]));
                m1 = fmaxf(m1, fmaxf(sfr[mb][nb][2], sfr[mb][nb][3]));
            }
            m0 = fmaxf(m0, __shfl_xor_sync(0xffffffffu, m0, 1));
            m0 = fmaxf(m0, __shfl_xor_sync(0xffffffffu, m0, 2));
            m1 = fmaxf(m1, __shfl_xor_sync(0xffffffffu, m1, 1));
            m1 = fmaxf(m1, __shfl_xor_sync(0xffffffffu, m1, 2));
            if (t == 0) {
                pmax[(w>>1)*64 + wm + mb*16 + g    ] = m0;
                pmax[(w>>1)*64 + wm + mb*16 + g + 8] = m1;
            }
        }
        __syncthreads();

        if (it + 1 < 16) issueK((it + 1) * 128);
        CPC;

        if (tid < 64) {
            int r = tid;
            float mt = fmaxf(fmaxf(pmax[r], pmax[64+r]), fmaxf(pmax[128+r], pmax[192+r]));
            float m_old = m_s[r];
            float m_new = fmaxf(m_old, mt);
            float rs = __expf(m_old - m_new);
            rs_s[r] = rs; m_s[r] = m_new; l_s[r] *= rs;
        }
        __syncthreads();

        // ---- exp, P->smem (fp16 hi only), partial sums; rescale acc ----
        float ps[2][2] = {{0.f,0.f},{0.f,0.f}};
        #pragma unroll
        for (int mb = 0; mb < 2; mb++) {
            int row0 = wm + mb*16 + g;
            float m0 = m_s[row0], m1 = m_s[row0 + 8];
            #pragma unroll
            for (int nb = 0; nb < 4; nb++) {
                int pp = (wn >> 1) + nb*4 + t;
                float p0 = __expf(sfr[mb][nb][0] - m0);
                float p1 = __expf(sfr[mb][nb][1] - m0);
                float p2 = __expf(sfr[mb][nb][2] - m1);
                float p3 = __expf(sfr[mb][nb][3] - m1);
                ps[mb][0] += p0 + p1;
                ps[mb][1] += p2 + p3;
                Ph[row0*AP + pp]     = cvth(p0, p1);
                Ph[(row0+8)*AP + pp] = cvth(p2, p3);
            }
            ps[mb][0] += __shfl_xor_sync(0xffffffffu, ps[mb][0], 1);
            ps[mb][0] += __shfl_xor_sync(0xffffffffu, ps[mb][0], 2);
            ps[mb][1] += __shfl_xor_sync(0xffffffffu, ps[mb][1], 1);
            ps[mb][1] += __shfl_xor_sync(0xffffffffu, ps[mb][1], 2);
            if (t == 0) {
                psum[(w>>1)*64 + wm + mb*16 + g    ] = ps[mb][0];
                psum[(w>>1)*64 + wm + mb*16 + g + 8] = ps[mb][1];
            }
        }
        #pragma unroll
        for (int mb = 0; mb < 2; mb++) {
            int row0 = wm + mb*16 + g;
            float r0 = rs_s[row0], r1 = rs_s[row0 + 8];
            #pragma unroll
            for (int nb = 0; nb < 4; nb++) {
                acc[mb][nb][0] *= r0; acc[mb][nb][1] *= r0;
                acc[mb][nb][2] *= r1; acc[mb][nb][3] *= r1;
            }
        }
        if (it < 15) { CPW1; } else { CPW0; }
        __syncthreads();
        if (tid < 64)
            l_s[tid] += psum[tid] + psum[64+tid] + psum[128+tid] + psum[192+tid];

        // ---- O += P V (plain fp16, 1 term) ----
        #pragma unroll
        for (int k16 = 0; k16 < 8; k16++) {
            uint32_t ah[2][4], bh[4][2];
            #pragma unroll
            for (int mb = 0; mb < 2; mb++)
                LDSM4(ah[mb][0], ah[mb][1], ah[mb][2], ah[mb][3],
                      aBase + PH_OFF*4 + mb*16*272 + k16*32);
            #pragma unroll
            for (int nbp = 0; nbp < 2; nbp++)
                LDSM4(bh[2*nbp][0], bh[2*nbp][1], bh[2*nbp+1][0], bh[2*nbp+1][1],
                      bBase + VH_OFF*4 + nbp*16*272 + k16*32);
            #pragma unroll
            for (int nb = 0; nb < 4; nb++)
                #pragma unroll
                for (int mb = 0; mb < 2; mb++)
                    mma_f16(acc[mb][nb], ah[mb], bh[nb]);
        }
        __syncthreads();

        if (it + 1 < 16) issueV((it + 1) * 128);
        CPC;
    }

    // ---- epilogue ----
    #pragma unroll
    for (int mb = 0; mb < 2; mb++) {
        int row0 = wm + mb*16 + g;
        float inv0 = 1.0f / l_s[row0];
        float inv1 = 1.0f / l_s[row0 + 8];
        #pragma unroll
        for (int nb = 0; nb < 4; nb++) {
            int col = h*HD_ + wn + nb*8 + 2*t;
            size_t o0 = (size_t)(b*T_ + q0 + row0) * D_ + col;
            size_t o1 = (size_t)(b*T_ + q0 + row0 + 8) * D_ + col;
            *(uint32_t*)(Oh_g + o0) = cvth(acc[mb][nb][0]*inv0, acc[mb][nb][1]*inv0);
            *(uint32_t*)(Oh_g + o1) = cvth(acc[mb][nb][2]*inv1, acc[mb][nb][3]*inv1);
        }
    }
}

// ---------------- launch ------------------------------------------------------
extern "C" void kernel_launch(void* const* d_in, const int* in_sizes, int n_in,
                              void* d_out, int out_size)
{
    const float* x  = (const float*)d_in[0];
    const float* wq = (const float*)d_in[1];
    const float* wk = (const float*)d_in[2];
    const float* wv = (const float*)d_in[3];
    const float* wo = (const float*)d_in[4];
    float* out = (float*)d_out;

    float *pQKV;
    __half *pXh, *pW3h, *pW3l, *pWoh, *pWol;
    __half *pQh, *pQl, *pKh, *pKl, *pVth, *pOh;
    cudaGetSymbolAddress((void**)&pQKV, g_QKVf);
    cudaGetSymbolAddress((void**)&pXh, g_Xh);
    cudaGetSymbolAddress((void**)&pW3h, g_W3h); cudaGetSymbolAddress((void**)&pW3l, g_W3l);
    cudaGetSymbolAddress((void**)&pWoh, g_Woh); cudaGetSymbolAddress((void**)&pWol, g_Wol);
    cudaGetSymbolAddress((void**)&pQh, g_Qh);   cudaGetSymbolAddress((void**)&pQl, g_Ql);
    cudaGetSymbolAddress((void**)&pKh, g_Kh2);  cudaGetSymbolAddress((void**)&pKl, g_Kl2);
    cudaGetSymbolAddress((void**)&pVth, g_Vth);
    cudaGetSymbolAddress((void**)&pOh, g_Oh);

    cudaFuncSetAttribute(gemm_2t, cudaFuncAttributeMaxDynamicSharedMemorySize, G2_BYTES);
    cudaFuncSetAttribute(flash_attn_h3, cudaFuncAttributeMaxDynamicSharedMemorySize, FA_SMEM_BYTES);

    split_hi<<<(M_*D_/4)/256, 256>>>(x, pXh, M_*D_/4);
    split_f32<<<(D_*D_/4)/256,   256>>>(wq, pW3h,                      pW3l,                      D_*D_/4);
    split_f32<<<(KVD_*D_/4)/256, 256>>>(wk, pW3h + (size_t)2048*2048,  pW3l + (size_t)2048*2048,  KVD_*D_/4);
    split_f32<<<(KVD_*D_/4)/256, 256>>>(wv, pW3h + (size_t)2560*2048,  pW3l + (size_t)2560*2048,  KVD_*D_/4);
    split_f32<<<(D_*D_/4)/256,   256>>>(wo, pWoh, pWol, D_*D_/4);

    gemm_2t<<<dim3(NQKV/128, M_/128), 256, G2_BYTES>>>(pXh, pW3h, pW3l, pQKV, NQKV, D_);

    const float scale = 0.08838834764831845f;
    rope_split<<<(M_*H_*32)/256,  256>>>(pQKV, pQh, pQl, H_,  scale, NQKV, 0,    M_*H_*32);
    rope_split<<<(M_*KV_*32)/256, 256>>>(pQKV, pKh, pKl, KV_, 1.0f,  NQKV, 2048, M_*KV_*32);
    vtrans_split<<<dim3(T_/32, KVD_/32, B_), dim3(32, 8)>>>(pQKV, pVth);

    flash_attn_h3<<<dim3(T_/64, H_, B_), 256, FA_SMEM_BYTES>>>(
        pQh, pQl, pKh, pKl, pVth, pOh);

    gemm_2t<<<dim3(D_/128, M_/128), 256, G2_BYTES>>>(pOh, pWoh, pWol, out, D_, D_);
}

// round 11
// speedup vs baseline: 2.1588x; 1.2669x over previous
#include <cuda_runtime.h>
#include <cuda_fp16.h>
#include <cstdint>
#include <math.h>

#define B_  2
#define T_  2048
#define D_  2048
#define H_  16
#define KV_ 4
#define HD_ 128
#define M_  (B_*T_)    // 4096
#define KVD_ (KV_*HD_) // 512
#define NQKV 3072      // packed Q(2048) + K(512) + V(512)

// ---------------- scratch ----------------------------------------------------
__device__ float  g_QKVf[M_ * NQKV];
__device__ __half g_Xh[M_*D_];
__device__ __half g_W3h[NQKV*D_], g_W3l[NQKV*D_];
__device__ __half g_Woh[D_*D_],   g_Wol[D_*D_];
__device__ __half g_Qh[M_*D_];
__device__ __half g_Kh2[M_*KVD_];
__device__ __half g_Vth[M_*KVD_];                  // [(b*KV+g)*128+d][T], hi only
__device__ __half g_Oh[M_*D_];

// ---------------- helpers -----------------------------------------------------
__device__ __forceinline__ void cvt2(float x, float y, uint32_t& h, uint32_t& l) {
    __half2 hh = __floats2half2_rn(x, y);
    float2 hf = __half22float2(hh);
    __half2 ll = __floats2half2_rn(x - hf.x, y - hf.y);
    h = *reinterpret_cast<uint32_t*>(&hh);
    l = *reinterpret_cast<uint32_t*>(&ll);
}
__device__ __forceinline__ uint32_t cvth(float x, float y) {
    __half2 hh = __floats2half2_rn(x, y);
    return *reinterpret_cast<uint32_t*>(&hh);
}
__device__ __forceinline__ void mma_f16(float* c, const uint32_t* a, const uint32_t* b) {
    asm volatile(
        "mma.sync.aligned.m16n8k16.row.col.f32.f16.f16.f32 "
        "{%0,%1,%2,%3}, {%4,%5,%6,%7}, {%8,%9}, {%0,%1,%2,%3};"
        : "+f"(c[0]), "+f"(c[1]), "+f"(c[2]), "+f"(c[3])
        : "r"(a[0]), "r"(a[1]), "r"(a[2]), "r"(a[3]), "r"(b[0]), "r"(b[1]));
}
__device__ __forceinline__ uint32_t s2u(const void* p) {
    uint32_t a;
    asm("{ .reg .u64 t; cvta.to.shared.u64 t, %1; cvt.u32.u64 %0, t; }" : "=r"(a) : "l"(p));
    return a;
}
#define LDSM4(r0, r1, r2, r3, addr) \
    asm volatile("ldmatrix.sync.aligned.m8n8.x4.shared.b16 {%0,%1,%2,%3}, [%4];" \
        : "=r"(r0), "=r"(r1), "=r"(r2), "=r"(r3) : "r"(addr))
#define CP16(dst, src) asm volatile("cp.async.cg.shared.global [%0], [%1], 16;" :: "r"(dst), "l"(src))
#define CPC   asm volatile("cp.async.commit_group;" ::: "memory")
#define CPW0  asm volatile("cp.async.wait_group 0;" ::: "memory")
#define CPW1  asm volatile("cp.async.wait_group 1;" ::: "memory")

// ---------------- pre-split kernels -------------------------------------------
__global__ void split_f32(const float* __restrict__ X,
                          __half* __restrict__ Xh, __half* __restrict__ Xl, int n4)
{
    int i = blockIdx.x * blockDim.x + threadIdx.x;
    if (i >= n4) return;
    float4 v = *(const float4*)(X + (size_t)i * 4);
    uint32_t h0, l0, h1, l1;
    cvt2(v.x, v.y, h0, l0);
    cvt2(v.z, v.w, h1, l1);
    *(uint2*)(Xh + (size_t)i * 4) = make_uint2(h0, h1);
    *(uint2*)(Xl + (size_t)i * 4) = make_uint2(l0, l1);
}
__global__ void split_hi(const float* __restrict__ X, __half* __restrict__ Xh, int n4)
{
    int i = blockIdx.x * blockDim.x + threadIdx.x;
    if (i >= n4) return;
    float4 v = *(const float4*)(X + (size_t)i * 4);
    *(uint2*)(Xh + (size_t)i * 4) = make_uint2(cvth(v.x, v.y), cvth(v.z, v.w));
}

// RoPE -> fp16 hi only
__global__ void rope_hi(const float* __restrict__ X, __half* __restrict__ Xh,
                        int nheads, float scale, int in_ld, int in_off, int total)
{
    int idx = blockIdx.x * blockDim.x + threadIdx.x;
    if (idx >= total) return;
    int j2 = idx & 31;
    int hh = (idx >> 5) % nheads;
    int m  = idx / (32 * nheads);
    int t  = m & (T_ - 1);

    size_t ri = (size_t)m * in_ld + in_off + hh * HD_;
    size_t ro = (size_t)m * (nheads * HD_) + hh * HD_;
    float2 a  = *(const float2*)(X + ri + j2*2);
    float2 bq = *(const float2*)(X + ri + 64 + j2*2);

    float inv0 = powf(10000.0f, -((float)(2 * (2*j2))     / 128.0f));
    float inv1 = powf(10000.0f, -((float)(2 * (2*j2 + 1)) / 128.0f));
    float s0, c0, s1, c1;
    sincosf((float)t * inv0, &s0, &c0);
    sincosf((float)t * inv1, &s1, &c1);

    float o0 = (a.x * c0 - bq.x * s0) * scale;
    float o1 = (a.y * c1 - bq.y * s1) * scale;
    float o2 = (bq.x * c0 + a.x * s0) * scale;
    float o3 = (bq.y * c1 + a.y * s1) * scale;

    *(uint32_t*)(Xh + ro + j2*2)      = cvth(o0, o1);
    *(uint32_t*)(Xh + ro + 64 + j2*2) = cvth(o2, o3);
}

// V transpose: packed QKVf col 2560+ -> [(b*KV+g)*128+d][t] fp16 hi only
__global__ void vtrans_split(const float* __restrict__ QKV, __half* __restrict__ Vh)
{
    __shared__ float tile[32][33];
    int bx = blockIdx.x, by = blockIdx.y, b = blockIdx.z;
    int tx = threadIdx.x, ty = threadIdx.y;
    #pragma unroll
    for (int i = 0; i < 4; i++) {
        int tt = bx*32 + ty + i*8;
        int dd = by*32 + tx;
        tile[ty + i*8][tx] = QKV[(size_t)(b*T_ + tt) * NQKV + 2560 + dd];
    }
    __syncthreads();
    #pragma unroll
    for (int i = 0; i < 4; i++) {
        int dd = by*32 + ty + i*8;
        int tt = bx*32 + tx;
        float v = tile[tx][ty + i*8];
        Vh[(size_t)(b*KVD_ + dd) * T_ + tt] = __float2half_rn(v);
    }
}

// ============================================================================
// 2-term fp16 GEMM with ldmatrix fragment loads (unchanged from round 8).
// ============================================================================
#define G2_BYTES (2*3*2560*4)

__global__ __launch_bounds__(256) void gemm_2t(
    const __half* __restrict__ Ah_g,
    const __half* __restrict__ Bh_g, const __half* __restrict__ Bl_g,
    float* __restrict__ C, int ldc, int K)
{
    extern __shared__ uint32_t su[];
    const uint32_t sb = s2u(su);
    const int tid = threadIdx.x, lane = tid & 31, w = tid >> 5;
    const int bm = blockIdx.y * 128, bn = blockIdx.x * 128;
    const int wm = (w & 1) * 64;
    const int wn = (w >> 1) * 32;
    const int g = lane >> 2, t = lane & 3;

    const int matid = tid >> 6;
    const __half* gp = (matid == 0) ? Ah_g : (matid == 1) ? Bh_g : Bl_g;
    const int rowb = (matid == 0) ? bm : bn;
    const int t64 = tid & 63;
    const int rb0 = t64 >> 2, cc = t64 & 3;
    const uint32_t dstb = sb + matid*10240 + rb0*80 + cc*16;
    const __half* srcb = gp + (size_t)(rowb + rb0) * K + cc * 8;
    const bool loader = (matid < 3);

    const int arow = wm + ((lane >> 3) & 1) * 8 + (lane & 7);
    const uint32_t aBase = sb + arow * 80 + (lane >> 4) * 16;
    const int brow = wn + (lane >> 4) * 8 + (lane & 7);
    const uint32_t bBase = sb + 10240 + brow * 80 + ((lane >> 3) & 1) * 16;

    float acc[4][4][4];
    #pragma unroll
    for (int mb = 0; mb < 4; mb++)
        #pragma unroll
        for (int nb = 0; nb < 4; nb++)
            #pragma unroll
            for (int i = 0; i < 4; i++) acc[mb][nb][i] = 0.f;

    if (loader) {
        #pragma unroll
        for (int i = 0; i < 8; i++)
            CP16(dstb + i*1280, srcb + (size_t)(16*i) * K);
    }
    CPC;

    const int NT = K >> 5;
    for (int kt = 0; kt < NT; kt++) {
        const int stg = kt & 1;
        const uint32_t stgoff = stg * 30720;
        CPW0;
        __syncthreads();
        if (kt + 1 < NT && loader) {
            const __half* s = srcb + (kt + 1) * 32;
            const uint32_t d2 = dstb + (stg ^ 1) * 30720;
            #pragma unroll
            for (int i = 0; i < 8; i++)
                CP16(d2 + i*1280, s + (size_t)(16*i) * K);
        }
        CPC;

        #pragma unroll
        for (int ks = 0; ks < 2; ks++) {
            uint32_t ah[4][4], bh[4][2], bl[4][2];
            #pragma unroll
            for (int mb = 0; mb < 4; mb++)
                LDSM4(ah[mb][0], ah[mb][1], ah[mb][2], ah[mb][3],
                      aBase + stgoff + mb*1280 + ks*32);
            #pragma unroll
            for (int nbp = 0; nbp < 2; nbp++) {
                LDSM4(bh[2*nbp][0], bh[2*nbp][1], bh[2*nbp+1][0], bh[2*nbp+1][1],
                      bBase + stgoff + nbp*1280 + ks*32);
                LDSM4(bl[2*nbp][0], bl[2*nbp][1], bl[2*nbp+1][0], bl[2*nbp+1][1],
                      bBase + stgoff + 10240 + nbp*1280 + ks*32);
            }
            #pragma unroll
            for (int nb = 0; nb < 4; nb++)
                #pragma unroll
                for (int mb = 0; mb < 4; mb++) {
                    mma_f16(acc[mb][nb], ah[mb], bh[nb]);
                    mma_f16(acc[mb][nb], ah[mb], bl[nb]);
                }
        }
    }

    #pragma unroll
    for (int mb = 0; mb < 4; mb++) {
        int r0 = bm + wm + mb * 16 + g;
        #pragma unroll
        for (int nb = 0; nb < 4; nb++) {
            int ccn = bn + wn + nb * 8 + 2 * t;
            *(float2*)(C + (size_t)r0 * ldc + ccn)       = make_float2(acc[mb][nb][0], acc[mb][nb][1]);
            *(float2*)(C + (size_t)(r0 + 8) * ldc + ccn) = make_float2(acc[mb][nb][2], acc[mb][nb][3]);
        }
    }
}

// ============================================================================
// flash attention: plain fp16 QK and PV, fp32 softmax. Round-8 structure.
// Smem ~107 KB -> up to 2 CTAs/SM.
// ============================================================================
#define AP 68
#define QH_OFF 0
#define KH_OFF (64*AP)
#define VH_OFF (192*AP)
#define PH_OFF (320*AP)
#define ST_OFF (384*AP)
#define FA_SMEM_BYTES ((ST_OFF + 64*3 + 4*64*2) * 4)   // ~107 KB

__global__ __launch_bounds__(256) void flash_attn_h1(
    const __half* __restrict__ Qh_g,
    const __half* __restrict__ Kh_g,
    const __half* __restrict__ Vh_g,
    __half* __restrict__ Oh_g)
{
    extern __shared__ uint32_t su[];
    const uint32_t sb = s2u(su);
    uint32_t* Ph = su + PH_OFF;
    float* m_s  = (float*)(su + ST_OFF);
    float* l_s  = m_s + 64;
    float* rs_s = l_s + 64;
    float* pmax = rs_s + 64;
    float* psum = pmax + 4*64;

    const int tid = threadIdx.x, lane = tid & 31, w = tid >> 5;
    const int qt = blockIdx.x, h = blockIdx.y, b = blockIdx.z;
    const int gq = h >> 2;
    const int q0 = qt * 64;
    const int wm = (w & 1) * 32;
    const int wn = (w >> 1) * 32;
    const int g = lane >> 2, t = lane & 3;

    // loader decomposition: all 256 threads, 16x16 grid of 16B chunks
    const int vr = tid >> 4, vc = tid & 15;    // vr 0..15, vc 0..15

    auto issueK = [&](int s0k) {
        const __half* src = Kh_g + (size_t)(b*T_ + s0k + vr) * KVD_ + gq*HD_ + vc*8;
        uint32_t dst = sb + (uint32_t)KH_OFF*4 + vr*272 + vc*16;
        #pragma unroll
        for (int i = 0; i < 8; i++)
            CP16(dst + i*16*272, src + (size_t)(16*i) * KVD_);
    };
    auto issueV = [&](int s0v) {
        const __half* src = Vh_g + ((size_t)(b*KV_ + gq)*HD_ + vr) * T_ + s0v + vc*8;
        uint32_t dst = sb + (uint32_t)VH_OFF*4 + vr*272 + vc*16;
        #pragma unroll
        for (int i = 0; i < 8; i++)
            CP16(dst + i*16*272, src + (size_t)(16*i) * T_);
    };

    {
        const __half* src = Qh_g + (size_t)(b*T_ + q0 + vr) * D_ + h*HD_ + vc*8;
        uint32_t dst = sb + (uint32_t)QH_OFF*4 + vr*272 + vc*16;
        #pragma unroll
        for (int i = 0; i < 4; i++)
            CP16(dst + i*16*272, src + (size_t)(16*i) * D_);
        issueK(0);
    }
    CPC;
    issueV(0);
    CPC;

    if (tid < 64) { m_s[tid] = -INFINITY; l_s[tid] = 0.f; }

    float acc[2][4][4];
    #pragma unroll
    for (int mb = 0; mb < 2; mb++)
        #pragma unroll
        for (int nb = 0; nb < 4; nb++)
            #pragma unroll
            for (int i = 0; i < 4; i++) acc[mb][nb][i] = 0.f;

    // ldmatrix per-lane bases
    const int arow = wm + ((lane >> 3) & 1) * 8 + (lane & 7);
    const uint32_t aBase = sb + arow * 272 + (lane >> 4) * 16;
    const int brow = wn + (lane >> 4) * 8 + (lane & 7);
    const uint32_t bBase = sb + brow * 272 + ((lane >> 3) & 1) * 16;

    for (int it = 0; it < 16; it++) {
        CPW1;
        __syncthreads();

        // ---- S = Q K^T (plain fp16) ----
        float sfr[2][4][4];
        #pragma unroll
        for (int mb = 0; mb < 2; mb++)
            #pragma unroll
            for (int nb = 0; nb < 4; nb++)
                #pragma unroll
                for (int i = 0; i < 4; i++) sfr[mb][nb][i] = 0.f;

        #pragma unroll
        for (int k16 = 0; k16 < 8; k16++) {
            uint32_t ah[2][4], bh[4][2];
            #pragma unroll
            for (int mb = 0; mb < 2; mb++)
                LDSM4(ah[mb][0], ah[mb][1], ah[mb][2], ah[mb][3],
                      aBase + QH_OFF*4 + mb*16*272 + k16*32);
            #pragma unroll
            for (int nbp = 0; nbp < 2; nbp++)
                LDSM4(bh[2*nbp][0], bh[2*nbp][1], bh[2*nbp+1][0], bh[2*nbp+1][1],
                      bBase + KH_OFF*4 + nbp*16*272 + k16*32);
            #pragma unroll
            for (int nb = 0; nb < 4; nb++)
                #pragma unroll
                for (int mb = 0; mb < 2; mb++)
                    mma_f16(sfr[mb][nb], ah[mb], bh[nb]);
        }

        // ---- row max ----
        #pragma unroll
        for (int mb = 0; mb < 2; mb++) {
            float m0 = -INFINITY, m1 = -INFINITY;
            #pragma unroll
            for (int nb = 0; nb < 4; nb++) {
                m0 = fmaxf(m0, fmaxf(sfr[mb][nb][0], sfr[mb][nb][1]));
                m1 = fmaxf(m1, fmaxf(sfr[mb][nb][2], sfr[mb][nb][3]));
            }
            m0 = fmaxf(m0, __shfl_xor_sync(0xffffffffu, m0, 1));
            m0 = fmaxf(m0, __shfl_xor_sync(0xffffffffu, m0, 2));
            m1 = fmaxf(m1, __shfl_xor_sync(0xffffffffu, m1, 1));
            m1 = fmaxf(m1, __shfl_xor_sync(0xffffffffu, m1, 2));
            if (t == 0) {
                pmax[(w>>1)*64 + wm + mb*16 + g    ] = m0;
                pmax[(w>>1)*64 + wm + mb*16 + g + 8] = m1;
            }
        }
        __syncthreads();

        if (it + 1 < 16) issueK((it + 1) * 128);
        CPC;

        if (tid < 64) {
            int r = tid;
            float mt = fmaxf(fmaxf(pmax[r], pmax[64+r]), fmaxf(pmax[128+r], pmax[192+r]));
            float m_old = m_s[r];
            float m_new = fmaxf(m_old, mt);
            float rs = __expf(m_old - m_new);
            rs_s[r] = rs; m_s[r] = m_new; l_s[r] *= rs;
        }
        __syncthreads();

        // ---- exp, P->smem (fp16), partial sums; rescale acc ----
        float ps[2][2] = {{0.f,0.f},{0.f,0.f}};
        #pragma unroll
        for (int mb = 0; mb < 2; mb++) {
            int row0 = wm + mb*16 + g;
            float m0 = m_s[row0], m1 = m_s[row0 + 8];
            #pragma unroll
            for (int nb = 0; nb < 4; nb++) {
                int pp = (wn >> 1) + nb*4 + t;
                float p0 = __expf(sfr[mb][nb][0] - m0);
                float p1 = __expf(sfr[mb][nb][1] - m0);
                float p2 = __expf(sfr[mb][nb][2] - m1);
                float p3 = __expf(sfr[mb][nb][3] - m1);
                ps[mb][0] += p0 + p1;
                ps[mb][1] += p2 + p3;
                Ph[row0*AP + pp]     = cvth(p0, p1);
                Ph[(row0+8)*AP + pp] = cvth(p2, p3);
            }
            ps[mb][0] += __shfl_xor_sync(0xffffffffu, ps[mb][0], 1);
            ps[mb][0] += __shfl_xor_sync(0xffffffffu, ps[mb][0], 2);
            ps[mb][1] += __shfl_xor_sync(0xffffffffu, ps[mb][1], 1);
            ps[mb][1] += __shfl_xor_sync(0xffffffffu, ps[mb][1], 2);
            if (t == 0) {
                psum[(w>>1)*64 + wm + mb*16 + g    ] = ps[mb][0];
                psum[(w>>1)*64 + wm + mb*16 + g + 8] = ps[mb][1];
            }
        }
        #pragma unroll
        for (int mb = 0; mb < 2; mb++) {
            int row0 = wm + mb*16 + g;
            float r0 = rs_s[row0], r1 = rs_s[row0 + 8];
            #pragma unroll
            for (int nb = 0; nb < 4; nb++) {
                acc[mb][nb][0] *= r0; acc[mb][nb][1] *= r0;
                acc[mb][nb][2] *= r1; acc[mb][nb][3] *= r1;
            }
        }
        if (it < 15) { CPW1; } else { CPW0; }
        __syncthreads();
        if (tid < 64)
            l_s[tid] += psum[tid] + psum[64+tid] + psum[128+tid] + psum[192+tid];

        // ---- O += P V (plain fp16) ----
        #pragma unroll
        for (int k16 = 0; k16 < 8; k16++) {
            uint32_t ah[2][4], bh[4][2];
            #pragma unroll
            for (int mb = 0; mb < 2; mb++)
                LDSM4(ah[mb][0], ah[mb][1], ah[mb][2], ah[mb][3],
                      aBase + PH_OFF*4 + mb*16*272 + k16*32);
            #pragma unroll
            for (int nbp = 0; nbp < 2; nbp++)
                LDSM4(bh[2*nbp][0], bh[2*nbp][1], bh[2*nbp+1][0], bh[2*nbp+1][1],
                      bBase + VH_OFF*4 + nbp*16*272 + k16*32);
            #pragma unroll
            for (int nb = 0; nb < 4; nb++)
                #pragma unroll
                for (int mb = 0; mb < 2; mb++)
                    mma_f16(acc[mb][nb], ah[mb], bh[nb]);
        }
        __syncthreads();

        if (it + 1 < 16) issueV((it + 1) * 128);
        CPC;
    }

    // ---- epilogue ----
    #pragma unroll
    for (int mb = 0; mb < 2; mb++) {
        int row0 = wm + mb*16 + g;
        float inv0 = 1.0f / l_s[row0];
        float inv1 = 1.0f / l_s[row0 + 8];
        #pragma unroll
        for (int nb = 0; nb < 4; nb++) {
            int col = h*HD_ + wn + nb*8 + 2*t;
            size_t o0 = (size_t)(b*T_ + q0 + row0) * D_ + col;
            size_t o1 = (size_t)(b*T_ + q0 + row0 + 8) * D_ + col;
            *(uint32_t*)(Oh_g + o0) = cvth(acc[mb][nb][0]*inv0, acc[mb][nb][1]*inv0);
            *(uint32_t*)(Oh_g + o1) = cvth(acc[mb][nb][2]*inv1, acc[mb][nb][3]*inv1);
        }
    }
}

// ---------------- launch ------------------------------------------------------
extern "C" void kernel_launch(void* const* d_in, const int* in_sizes, int n_in,
                              void* d_out, int out_size)
{
    const float* x  = (const float*)d_in[0];
    const float* wq = (const float*)d_in[1];
    const float* wk = (const float*)d_in[2];
    const float* wv = (const float*)d_in[3];
    const float* wo = (const float*)d_in[4];
    float* out = (float*)d_out;

    float *pQKV;
    __half *pXh, *pW3h, *pW3l, *pWoh, *pWol;
    __half *pQh, *pKh, *pVth, *pOh;
    cudaGetSymbolAddress((void**)&pQKV, g_QKVf);
    cudaGetSymbolAddress((void**)&pXh, g_Xh);
    cudaGetSymbolAddress((void**)&pW3h, g_W3h); cudaGetSymbolAddress((void**)&pW3l, g_W3l);
    cudaGetSymbolAddress((void**)&pWoh, g_Woh); cudaGetSymbolAddress((void**)&pWol, g_Wol);
    cudaGetSymbolAddress((void**)&pQh, g_Qh);
    cudaGetSymbolAddress((void**)&pKh, g_Kh2);
    cudaGetSymbolAddress((void**)&pVth, g_Vth);
    cudaGetSymbolAddress((void**)&pOh, g_Oh);

    cudaFuncSetAttribute(gemm_2t, cudaFuncAttributeMaxDynamicSharedMemorySize, G2_BYTES);
    cudaFuncSetAttribute(flash_attn_h1, cudaFuncAttributeMaxDynamicSharedMemorySize, FA_SMEM_BYTES);

    split_hi<<<(M_*D_/4)/256, 256>>>(x, pXh, M_*D_/4);
    split_f32<<<(D_*D_/4)/256,   256>>>(wq, pW3h,                      pW3l,                      D_*D_/4);
    split_f32<<<(KVD_*D_/4)/256, 256>>>(wk, pW3h + (size_t)2048*2048,  pW3l + (size_t)2048*2048,  KVD_*D_/4);
    split_f32<<<(KVD_*D_/4)/256, 256>>>(wv, pW3h + (size_t)2560*2048,  pW3l + (size_t)2560*2048,  KVD_*D_/4);
    split_f32<<<(D_*D_/4)/256,   256>>>(wo, pWoh, pWol, D_*D_/4);

    gemm_2t<<<dim3(NQKV/128, M_/128), 256, G2_BYTES>>>(pXh, pW3h, pW3l, pQKV, NQKV, D_);

    const float scale = 0.08838834764831845f;
    rope_hi<<<(M_*H_*32)/256,  256>>>(pQKV, pQh, H_,  scale, NQKV, 0,    M_*H_*32);
    rope_hi<<<(M_*KV_*32)/256, 256>>>(pQKV, pKh, KV_, 1.0f,  NQKV, 2048, M_*KV_*32);
    vtrans_split<<<dim3(T_/32, KVD_/32, B_), dim3(32, 8)>>>(pQKV, pVth);

    flash_attn_h1<<<dim3(T_/64, H_, B_), 256, FA_SMEM_BYTES>>>(pQh, pKh, pVth, pOh);

    gemm_2t<<<dim3(D_/128, M_/128), 256, G2_BYTES>>>(pOh, pWoh, pWol, out, D_, D_);
}

// round 12
// speedup vs baseline: 2.2215x; 1.0290x over previous
#include <cuda_runtime.h>
#include <cuda_fp16.h>
#include <cstdint>
#include <math.h>

#define B_  2
#define T_  2048
#define D_  2048
#define H_  16
#define KV_ 4
#define HD_ 128
#define M_  (B_*T_)    // 4096
#define KVD_ (KV_*HD_) // 512
#define NQKV 3072      // packed Q(2048) + K(512) + V(512)

// ---------------- scratch ----------------------------------------------------
__device__ __half g_Xh[M_*D_];
__device__ __half g_W3h[NQKV*D_], g_W3l[NQKV*D_];
__device__ __half g_Woh[D_*D_],   g_Wol[D_*D_];
__device__ __half g_Qh[M_*D_];
__device__ __half g_Kh2[M_*KVD_];
__device__ __half g_Vth[M_*KVD_];                  // [(b*KV+g)*128+d][T]
__device__ __half g_Oh[M_*D_];

// ---------------- helpers -----------------------------------------------------
__device__ __forceinline__ void cvt2(float x, float y, uint32_t& h, uint32_t& l) {
    __half2 hh = __floats2half2_rn(x, y);
    float2 hf = __half22float2(hh);
    __half2 ll = __floats2half2_rn(x - hf.x, y - hf.y);
    h = *reinterpret_cast<uint32_t*>(&hh);
    l = *reinterpret_cast<uint32_t*>(&ll);
}
__device__ __forceinline__ uint32_t cvth(float x, float y) {
    __half2 hh = __floats2half2_rn(x, y);
    return *reinterpret_cast<uint32_t*>(&hh);
}
__device__ __forceinline__ void mma_f16(float* c, const uint32_t* a, const uint32_t* b) {
    asm volatile(
        "mma.sync.aligned.m16n8k16.row.col.f32.f16.f16.f32 "
        "{%0,%1,%2,%3}, {%4,%5,%6,%7}, {%8,%9}, {%0,%1,%2,%3};"
        : "+f"(c[0]), "+f"(c[1]), "+f"(c[2]), "+f"(c[3])
        : "r"(a[0]), "r"(a[1]), "r"(a[2]), "r"(a[3]), "r"(b[0]), "r"(b[1]));
}
__device__ __forceinline__ uint32_t s2u(const void* p) {
    uint32_t a;
    asm("{ .reg .u64 t; cvta.to.shared.u64 t, %1; cvt.u32.u64 %0, t; }" : "=r"(a) : "l"(p));
    return a;
}
#define LDSM4(r0, r1, r2, r3, addr) \
    asm volatile("ldmatrix.sync.aligned.m8n8.x4.shared.b16 {%0,%1,%2,%3}, [%4];" \
        : "=r"(r0), "=r"(r1), "=r"(r2), "=r"(r3) : "r"(addr))
#define CP16(dst, src) asm volatile("cp.async.cg.shared.global [%0], [%1], 16;" :: "r"(dst), "l"(src))
#define CPC   asm volatile("cp.async.commit_group;" ::: "memory")
#define CPW0  asm volatile("cp.async.wait_group 0;" ::: "memory")
#define CPW1  asm volatile("cp.async.wait_group 1;" ::: "memory")

// ---------------- pre-split kernels -------------------------------------------
__global__ void split_f32(const float* __restrict__ X,
                          __half* __restrict__ Xh, __half* __restrict__ Xl, int n4)
{
    int i = blockIdx.x * blockDim.x + threadIdx.x;
    if (i >= n4) return;
    float4 v = *(const float4*)(X + (size_t)i * 4);
    uint32_t h0, l0, h1, l1;
    cvt2(v.x, v.y, h0, l0);
    cvt2(v.z, v.w, h1, l1);
    *(uint2*)(Xh + (size_t)i * 4) = make_uint2(h0, h1);
    *(uint2*)(Xl + (size_t)i * 4) = make_uint2(l0, l1);
}
__global__ void split_hi(const float* __restrict__ X, __half* __restrict__ Xh, int n4)
{
    int i = blockIdx.x * blockDim.x + threadIdx.x;
    if (i >= n4) return;
    float4 v = *(const float4*)(X + (size_t)i * 4);
    *(uint2*)(Xh + (size_t)i * 4) = make_uint2(cvth(v.x, v.y), cvth(v.z, v.w));
}

// ============================================================================
// Shared GEMM mainloop (2-term fp16, cp.async double-buffered, LDSM).
// Computes the 128x128 f32 accumulator tile; epilogue differs per kernel.
// ============================================================================
#define G2_BYTES 67584   // max(pipeline 61440, epilogue f32 tile 128*132*4)
#define TP 132           // epilogue tile stride (floats)

struct GemmCtx {
    float acc[4][4][4];
    int wm, wn, g, t;
};

__device__ __forceinline__ void gemm_mainloop(
    const __half* __restrict__ Ah_g,
    const __half* __restrict__ Bh_g, const __half* __restrict__ Bl_g,
    int K, int bm, int bn, uint32_t* su, uint32_t sb, GemmCtx& cx)
{
    const int tid = threadIdx.x, lane = tid & 31, w = tid >> 5;
    cx.wm = (w & 1) * 64;
    cx.wn = (w >> 1) * 32;
    cx.g = lane >> 2; cx.t = lane & 3;

    const int matid = tid >> 6;
    const __half* gp = (matid == 0) ? Ah_g : (matid == 1) ? Bh_g : Bl_g;
    const int rowb = (matid == 0) ? bm : bn;
    const int t64 = tid & 63;
    const int rb0 = t64 >> 2, cc = t64 & 3;
    const uint32_t dstb = sb + matid*10240 + rb0*80 + cc*16;
    const __half* srcb = gp + (size_t)(rowb + rb0) * K + cc * 8;
    const bool loader = (matid < 3);

    const int arow = cx.wm + ((lane >> 3) & 1) * 8 + (lane & 7);
    const uint32_t aBase = sb + arow * 80 + (lane >> 4) * 16;
    const int brow = cx.wn + (lane >> 4) * 8 + (lane & 7);
    const uint32_t bBase = sb + 10240 + brow * 80 + ((lane >> 3) & 1) * 16;

    #pragma unroll
    for (int mb = 0; mb < 4; mb++)
        #pragma unroll
        for (int nb = 0; nb < 4; nb++)
            #pragma unroll
            for (int i = 0; i < 4; i++) cx.acc[mb][nb][i] = 0.f;

    if (loader) {
        #pragma unroll
        for (int i = 0; i < 8; i++)
            CP16(dstb + i*1280, srcb + (size_t)(16*i) * K);
    }
    CPC;

    const int NT = K >> 5;
    for (int kt = 0; kt < NT; kt++) {
        const int stg = kt & 1;
        const uint32_t stgoff = stg * 30720;
        CPW0;
        __syncthreads();
        if (kt + 1 < NT && loader) {
            const __half* s = srcb + (kt + 1) * 32;
            const uint32_t d2 = dstb + (stg ^ 1) * 30720;
            #pragma unroll
            for (int i = 0; i < 8; i++)
                CP16(d2 + i*1280, s + (size_t)(16*i) * K);
        }
        CPC;

        #pragma unroll
        for (int ks = 0; ks < 2; ks++) {
            uint32_t ah[4][4], bh[4][2], bl[4][2];
            #pragma unroll
            for (int mb = 0; mb < 4; mb++)
                LDSM4(ah[mb][0], ah[mb][1], ah[mb][2], ah[mb][3],
                      aBase + stgoff + mb*1280 + ks*32);
            #pragma unroll
            for (int nbp = 0; nbp < 2; nbp++) {
                LDSM4(bh[2*nbp][0], bh[2*nbp][1], bh[2*nbp+1][0], bh[2*nbp+1][1],
                      bBase + stgoff + nbp*1280 + ks*32);
                LDSM4(bl[2*nbp][0], bl[2*nbp][1], bl[2*nbp+1][0], bl[2*nbp+1][1],
                      bBase + stgoff + 10240 + nbp*1280 + ks*32);
            }
            #pragma unroll
            for (int nb = 0; nb < 4; nb++)
                #pragma unroll
                for (int mb = 0; mb < 4; mb++) {
                    mma_f16(cx.acc[mb][nb], ah[mb], bh[nb]);
                    mma_f16(cx.acc[mb][nb], ah[mb], bl[nb]);
                }
        }
    }
}

// ---- WO projection GEMM: plain f32 output -----------------------------------
__global__ __launch_bounds__(256) void gemm_2t(
    const __half* __restrict__ Ah_g,
    const __half* __restrict__ Bh_g, const __half* __restrict__ Bl_g,
    float* __restrict__ C, int ldc, int K)
{
    extern __shared__ uint32_t su[];
    const uint32_t sb = s2u(su);
    const int bm = blockIdx.y * 128, bn = blockIdx.x * 128;
    GemmCtx cx;
    gemm_mainloop(Ah_g, Bh_g, Bl_g, K, bm, bn, su, sb, cx);

    #pragma unroll
    for (int mb = 0; mb < 4; mb++) {
        int r0 = bm + cx.wm + mb * 16 + cx.g;
        #pragma unroll
        for (int nb = 0; nb < 4; nb++) {
            int ccn = bn + cx.wn + nb * 8 + 2 * cx.t;
            *(float2*)(C + (size_t)r0 * ldc + ccn)       = make_float2(cx.acc[mb][nb][0], cx.acc[mb][nb][1]);
            *(float2*)(C + (size_t)(r0 + 8) * ldc + ccn) = make_float2(cx.acc[mb][nb][2], cx.acc[mb][nb][3]);
        }
    }
}

// ---- fused QKV GEMM: epilogue applies RoPE (Q,K) / transpose (V), fp16 out --
__global__ __launch_bounds__(256) void gemm_qkv(
    const __half* __restrict__ Ah_g,
    const __half* __restrict__ Bh_g, const __half* __restrict__ Bl_g,
    __half* __restrict__ Qh, __half* __restrict__ Kh, __half* __restrict__ Vt)
{
    extern __shared__ uint32_t su[];
    const uint32_t sb = s2u(su);
    const int tid = threadIdx.x;
    const int bm = blockIdx.y * 128, bn = blockIdx.x * 128;
    GemmCtx cx;
    gemm_mainloop(Ah_g, Bh_g, Bl_g, D_, bm, bn, su, sb, cx);

    // stage f32 tile in smem (pipeline buffers are dead after mainloop)
    float* st = (float*)su;
    __syncthreads();
    #pragma unroll
    for (int mb = 0; mb < 4; mb++) {
        int r0 = cx.wm + mb * 16 + cx.g;
        #pragma unroll
        for (int nb = 0; nb < 4; nb++) {
            int ccn = cx.wn + nb * 8 + 2 * cx.t;
            *(float2*)(st + r0 * TP + ccn)       = make_float2(cx.acc[mb][nb][0], cx.acc[mb][nb][1]);
            *(float2*)(st + (r0 + 8) * TP + ccn) = make_float2(cx.acc[mb][nb][2], cx.acc[mb][nb][3]);
        }
    }
    __syncthreads();

    if (bn < 2048) {
        // -------- Q block: RoPE + scale, fp16 out --------
        const int hh = bn >> 7;
        const float scale = 0.08838834764831845f;
        for (int p = tid; p < 8192; p += 256) {
            int r = p >> 6, j = p & 63;
            int m = bm + r, tpos = m & (T_ - 1);
            float inv = powf(10000.0f, -((float)(2 * j) / 128.0f));
            float s, c;
            sincosf((float)tpos * inv, &s, &c);
            float x1 = st[r * TP + j], x2 = st[r * TP + j + 64];
            __half* dst = Qh + (size_t)m * D_ + hh * HD_;
            dst[j]      = __float2half_rn((x1 * c - x2 * s) * scale);
            dst[j + 64] = __float2half_rn((x2 * c + x1 * s) * scale);
        }
    } else if (bn < 2560) {
        // -------- K block: RoPE, fp16 out --------
        const int gg = (bn - 2048) >> 7;
        for (int p = tid; p < 8192; p += 256) {
            int r = p >> 6, j = p & 63;
            int m = bm + r, tpos = m & (T_ - 1);
            float inv = powf(10000.0f, -((float)(2 * j) / 128.0f));
            float s, c;
            sincosf((float)tpos * inv, &s, &c);
            float x1 = st[r * TP + j], x2 = st[r * TP + j + 64];
            __half* dst = Kh + (size_t)m * KVD_ + gg * HD_;
            dst[j]      = __float2half_rn(x1 * c - x2 * s);
            dst[j + 64] = __float2half_rn(x2 * c + x1 * s);
        }
    } else {
        // -------- V block: transpose, fp16 out (Vt[(b*KV+g)*128+d][t]) --------
        const int d0 = bn - 2560;                 // 0..511 step 128
        const int bb = bm >> 11;                  // batch
        const int t0 = bm & (T_ - 1);
        for (int p = tid; p < 16384; p += 256) {
            int dl = p >> 7, tl = p & 127;
            float v = st[tl * TP + dl];
            Vt[(size_t)(bb * KVD_ + d0 + dl) * T_ + t0 + tl] = __float2half_rn(v);
        }
    }
}

// ============================================================================
// flash attention: plain fp16 QK and PV, fp32 softmax (unchanged from R11).
// ============================================================================
#define AP 68
#define QH_OFF 0
#define KH_OFF (64*AP)
#define VH_OFF (192*AP)
#define PH_OFF (320*AP)
#define ST_OFF (384*AP)
#define FA_SMEM_BYTES ((ST_OFF + 64*3 + 4*64*2) * 4)   // ~107 KB

__global__ __launch_bounds__(256) void flash_attn_h1(
    const __half* __restrict__ Qh_g,
    const __half* __restrict__ Kh_g,
    const __half* __restrict__ Vh_g,
    __half* __restrict__ Oh_g)
{
    extern __shared__ uint32_t su[];
    const uint32_t sb = s2u(su);
    uint32_t* Ph = su + PH_OFF;
    float* m_s  = (float*)(su + ST_OFF);
    float* l_s  = m_s + 64;
    float* rs_s = l_s + 64;
    float* pmax = rs_s + 64;
    float* psum = pmax + 4*64;

    const int tid = threadIdx.x, lane = tid & 31, w = tid >> 5;
    const int qt = blockIdx.x, h = blockIdx.y, b = blockIdx.z;
    const int gq = h >> 2;
    const int q0 = qt * 64;
    const int wm = (w & 1) * 32;
    const int wn = (w >> 1) * 32;
    const int g = lane >> 2, t = lane & 3;

    const int vr = tid >> 4, vc = tid & 15;

    auto issueK = [&](int s0k) {
        const __half* src = Kh_g + (size_t)(b*T_ + s0k + vr) * KVD_ + gq*HD_ + vc*8;
        uint32_t dst = sb + (uint32_t)KH_OFF*4 + vr*272 + vc*16;
        #pragma unroll
        for (int i = 0; i < 8; i++)
            CP16(dst + i*16*272, src + (size_t)(16*i) * KVD_);
    };
    auto issueV = [&](int s0v) {
        const __half* src = Vh_g + ((size_t)(b*KV_ + gq)*HD_ + vr) * T_ + s0v + vc*8;
        uint32_t dst = sb + (uint32_t)VH_OFF*4 + vr*272 + vc*16;
        #pragma unroll
        for (int i = 0; i < 8; i++)
            CP16(dst + i*16*272, src + (size_t)(16*i) * T_);
    };

    {
        const __half* src = Qh_g + (size_t)(b*T_ + q0 + vr) * D_ + h*HD_ + vc*8;
        uint32_t dst = sb + (uint32_t)QH_OFF*4 + vr*272 + vc*16;
        #pragma unroll
        for (int i = 0; i < 4; i++)
            CP16(dst + i*16*272, src + (size_t)(16*i) * D_);
        issueK(0);
    }
    CPC;
    issueV(0);
    CPC;

    if (tid < 64) { m_s[tid] = -INFINITY; l_s[tid] = 0.f; }

    float acc[2][4][4];
    #pragma unroll
    for (int mb = 0; mb < 2; mb++)
        #pragma unroll
        for (int nb = 0; nb < 4; nb++)
            #pragma unroll
            for (int i = 0; i < 4; i++) acc[mb][nb][i] = 0.f;

    const int arow = wm + ((lane >> 3) & 1) * 8 + (lane & 7);
    const uint32_t aBase = sb + arow * 272 + (lane >> 4) * 16;
    const int brow = wn + (lane >> 4) * 8 + (lane & 7);
    const uint32_t bBase = sb + brow * 272 + ((lane >> 3) & 1) * 16;

    for (int it = 0; it < 16; it++) {
        CPW1;
        __syncthreads();

        float sfr[2][4][4];
        #pragma unroll
        for (int mb = 0; mb < 2; mb++)
            #pragma unroll
            for (int nb = 0; nb < 4; nb++)
                #pragma unroll
                for (int i = 0; i < 4; i++) sfr[mb][nb][i] = 0.f;

        #pragma unroll
        for (int k16 = 0; k16 < 8; k16++) {
            uint32_t ah[2][4], bh[4][2];
            #pragma unroll
            for (int mb = 0; mb < 2; mb++)
                LDSM4(ah[mb][0], ah[mb][1], ah[mb][2], ah[mb][3],
                      aBase + QH_OFF*4 + mb*16*272 + k16*32);
            #pragma unroll
            for (int nbp = 0; nbp < 2; nbp++)
                LDSM4(bh[2*nbp][0], bh[2*nbp][1], bh[2*nbp+1][0], bh[2*nbp+1][1],
                      bBase + KH_OFF*4 + nbp*16*272 + k16*32);
            #pragma unroll
            for (int nb = 0; nb < 4; nb++)
                #pragma unroll
                for (int mb = 0; mb < 2; mb++)
                    mma_f16(sfr[mb][nb], ah[mb], bh[nb]);
        }

        #pragma unroll
        for (int mb = 0; mb < 2; mb++) {
            float m0 = -INFINITY, m1 = -INFINITY;
            #pragma unroll
            for (int nb = 0; nb < 4; nb++) {
                m0 = fmaxf(m0, fmaxf(sfr[mb][nb][0], sfr[mb][nb][1]));
                m1 = fmaxf(m1, fmaxf(sfr[mb][nb][2], sfr[mb][nb][3]));
            }
            m0 = fmaxf(m0, __shfl_xor_sync(0xffffffffu, m0, 1));
            m0 = fmaxf(m0, __shfl_xor_sync(0xffffffffu, m0, 2));
            m1 = fmaxf(m1, __shfl_xor_sync(0xffffffffu, m1, 1));
            m1 = fmaxf(m1, __shfl_xor_sync(0xffffffffu, m1, 2));
            if (t == 0) {
                pmax[(w>>1)*64 + wm + mb*16 + g    ] = m0;
                pmax[(w>>1)*64 + wm + mb*16 + g + 8] = m1;
            }
        }
        __syncthreads();

        if (it + 1 < 16) issueK((it + 1) * 128);
        CPC;

        if (tid < 64) {
            int r = tid;
            float mt = fmaxf(fmaxf(pmax[r], pmax[64+r]), fmaxf(pmax[128+r], pmax[192+r]));
            float m_old = m_s[r];
            float m_new = fmaxf(m_old, mt);
            float rs = __expf(m_old - m_new);
            rs_s[r] = rs; m_s[r] = m_new; l_s[r] *= rs;
        }
        __syncthreads();

        float ps[2][2] = {{0.f,0.f},{0.f,0.f}};
        #pragma unroll
        for (int mb = 0; mb < 2; mb++) {
            int row0 = wm + mb*16 + g;
            float m0 = m_s[row0], m1 = m_s[row0 + 8];
            #pragma unroll
            for (int nb = 0; nb < 4; nb++) {
                int pp = (wn >> 1) + nb*4 + t;
                float p0 = __expf(sfr[mb][nb][0] - m0);
                float p1 = __expf(sfr[mb][nb][1] - m0);
                float p2 = __expf(sfr[mb][nb][2] - m1);
                float p3 = __expf(sfr[mb][nb][3] - m1);
                ps[mb][0] += p0 + p1;
                ps[mb][1] += p2 + p3;
                Ph[row0*AP + pp]     = cvth(p0, p1);
                Ph[(row0+8)*AP + pp] = cvth(p2, p3);
            }
            ps[mb][0] += __shfl_xor_sync(0xffffffffu, ps[mb][0], 1);
            ps[mb][0] += __shfl_xor_sync(0xffffffffu, ps[mb][0], 2);
            ps[mb][1] += __shfl_xor_sync(0xffffffffu, ps[mb][1], 1);
            ps[mb][1] += __shfl_xor_sync(0xffffffffu, ps[mb][1], 2);
            if (t == 0) {
                psum[(w>>1)*64 + wm + mb*16 + g    ] = ps[mb][0];
                psum[(w>>1)*64 + wm + mb*16 + g + 8] = ps[mb][1];
            }
        }
        #pragma unroll
        for (int mb = 0; mb < 2; mb++) {
            int row0 = wm + mb*16 + g;
            float r0 = rs_s[row0], r1 = rs_s[row0 + 8];
            #pragma unroll
            for (int nb = 0; nb < 4; nb++) {
                acc[mb][nb][0] *= r0; acc[mb][nb][1] *= r0;
                acc[mb][nb][2] *= r1; acc[mb][nb][3] *= r1;
            }
        }
        if (it < 15) { CPW1; } else { CPW0; }
        __syncthreads();
        if (tid < 64)
            l_s[tid] += psum[tid] + psum[64+tid] + psum[128+tid] + psum[192+tid];

        #pragma unroll
        for (int k16 = 0; k16 < 8; k16++) {
            uint32_t ah[2][4], bh[4][2];
            #pragma unroll
            for (int mb = 0; mb < 2; mb++)
                LDSM4(ah[mb][0], ah[mb][1], ah[mb][2], ah[mb][3],
                      aBase + PH_OFF*4 + mb*16*272 + k16*32);
            #pragma unroll
            for (int nbp = 0; nbp < 2; nbp++)
                LDSM4(bh[2*nbp][0], bh[2*nbp][1], bh[2*nbp+1][0], bh[2*nbp+1][1],
                      bBase + VH_OFF*4 + nbp*16*272 + k16*32);
            #pragma unroll
            for (int nb = 0; nb < 4; nb++)
                #pragma unroll
                for (int mb = 0; mb < 2; mb++)
                    mma_f16(acc[mb][nb], ah[mb], bh[nb]);
        }
        __syncthreads();

        if (it + 1 < 16) issueV((it + 1) * 128);
        CPC;
    }

    #pragma unroll
    for (int mb = 0; mb < 2; mb++) {
        int row0 = wm + mb*16 + g;
        float inv0 = 1.0f / l_s[row0];
        float inv1 = 1.0f / l_s[row0 + 8];
        #pragma unroll
        for (int nb = 0; nb < 4; nb++) {
            int col = h*HD_ + wn + nb*8 + 2*t;
            size_t o0 = (size_t)(b*T_ + q0 + row0) * D_ + col;
            size_t o1 = (size_t)(b*T_ + q0 + row0 + 8) * D_ + col;
            *(uint32_t*)(Oh_g + o0) = cvth(acc[mb][nb][0]*inv0, acc[mb][nb][1]*inv0);
            *(uint32_t*)(Oh_g + o1) = cvth(acc[mb][nb][2]*inv1, acc[mb][nb][3]*inv1);
        }
    }
}

// ---------------- launch ------------------------------------------------------
extern "C" void kernel_launch(void* const* d_in, const int* in_sizes, int n_in,
                              void* d_out, int out_size)
{
    const float* x  = (const float*)d_in[0];
    const float* wq = (const float*)d_in[1];
    const float* wk = (const float*)d_in[2];
    const float* wv = (const float*)d_in[3];
    const float* wo = (const float*)d_in[4];
    float* out = (float*)d_out;

    __half *pXh, *pW3h, *pW3l, *pWoh, *pWol;
    __half *pQh, *pKh, *pVth, *pOh;
    cudaGetSymbolAddress((void**)&pXh, g_Xh);
    cudaGetSymbolAddress((void**)&pW3h, g_W3h); cudaGetSymbolAddress((void**)&pW3l, g_W3l);
    cudaGetSymbolAddress((void**)&pWoh, g_Woh); cudaGetSymbolAddress((void**)&pWol, g_Wol);
    cudaGetSymbolAddress((void**)&pQh, g_Qh);
    cudaGetSymbolAddress((void**)&pKh, g_Kh2);
    cudaGetSymbolAddress((void**)&pVth, g_Vth);
    cudaGetSymbolAddress((void**)&pOh, g_Oh);

    cudaFuncSetAttribute(gemm_2t,  cudaFuncAttributeMaxDynamicSharedMemorySize, G2_BYTES);
    cudaFuncSetAttribute(gemm_qkv, cudaFuncAttributeMaxDynamicSharedMemorySize, G2_BYTES);
    cudaFuncSetAttribute(flash_attn_h1, cudaFuncAttributeMaxDynamicSharedMemorySize, FA_SMEM_BYTES);

    split_hi<<<(M_*D_/4)/256, 256>>>(x, pXh, M_*D_/4);
    split_f32<<<(D_*D_/4)/256,   256>>>(wq, pW3h,                      pW3l,                      D_*D_/4);
    split_f32<<<(KVD_*D_/4)/256, 256>>>(wk, pW3h + (size_t)2048*2048,  pW3l + (size_t)2048*2048,  KVD_*D_/4);
    split_f32<<<(KVD_*D_/4)/256, 256>>>(wv, pW3h + (size_t)2560*2048,  pW3l + (size_t)2560*2048,  KVD_*D_/4);
    split_f32<<<(D_*D_/4)/256,   256>>>(wo, pWoh, pWol, D_*D_/4);

    // fused QKV projection + RoPE + V-transpose
    gemm_qkv<<<dim3(NQKV/128, M_/128), 256, G2_BYTES>>>(pXh, pW3h, pW3l, pQh, pKh, pVth);

    flash_attn_h1<<<dim3(T_/64, H_, B_), 256, FA_SMEM_BYTES>>>(pQh, pKh, pVth, pOh);

    gemm_2t<<<dim3(D_/128, M_/128), 256, G2_BYTES>>>(pOh, pWoh, pWol, out, D_, D_);
}